// round 1
// baseline (speedup 1.0000x reference)
#include <cuda_runtime.h>
#include <math.h>

#define D_MODEL 2048
#define N_HEADS 32
#define N_KV    8
#define HD      64
#define SEQ     2048
#define BATCH   2
#define NTOK    (BATCH*SEQ)      /* 4096 */
#define QDIM    (N_HEADS*HD)     /* 2048 */
#define KVDIM   (N_KV*HD)        /* 512  */
#define ROPE_BASE 500000.0

/* scratch (static device memory — no allocations) */
__device__ float g_q [NTOK*QDIM];
__device__ float g_k [NTOK*KVDIM];
__device__ float g_v [NTOK*KVDIM];
__device__ float g_ao[NTOK*QDIM];
__device__ float g_cos[SEQ*(HD/2)];
__device__ float g_sin[SEQ*(HD/2)];

/* ------------------------------------------------------------------ */
/* RoPE tables (fp64 for accuracy, tiny cost)                          */
/* ------------------------------------------------------------------ */
__global__ void rope_table_kernel() {
    int i = blockIdx.x * blockDim.x + threadIdx.x;
    if (i >= SEQ * (HD/2)) return;
    int t = i / (HD/2);
    int j = i % (HD/2);
    double inv = pow((double)ROPE_BASE, -(double)(2*j) / (double)HD);
    double ang = (double)t * inv;
    g_cos[i] = (float)cos(ang);
    g_sin[i] = (float)sin(ang);
}

/* ------------------------------------------------------------------ */
/* RoPE apply (in-place on g_q and g_k)                                */
/* ------------------------------------------------------------------ */
__global__ __launch_bounds__(256) void rope_apply_kernel() {
    int tok = blockIdx.x;
    int s   = tok & (SEQ - 1);
    for (int pi = threadIdx.x; pi < (N_HEADS + N_KV) * (HD/2); pi += 256) {
        int head = pi >> 5;          /* /32 */
        int j    = pi & 31;
        float c  = g_cos[s*32 + j];
        float sn = g_sin[s*32 + j];
        float* buf; long base;
        if (head < N_HEADS) { buf = g_q; base = (long)tok*QDIM  + head*HD; }
        else                { buf = g_k; base = (long)tok*KVDIM + (head-N_HEADS)*HD; }
        float x1 = buf[base + j];
        float x2 = buf[base + j + 32];
        buf[base + j]      = x1*c - x2*sn;
        buf[base + j + 32] = x2*c + x1*sn;
    }
}

/* ------------------------------------------------------------------ */
/* SGEMM: C[M,N] = A[M,K] @ B[K,N], all row-major fp32.                */
/* 128x128 block, BK=8, 256 threads, 8x8 microtile.                    */
/* Requires M%128==0, N%128==0, K%8==0 (true for all our shapes).      */
/* ------------------------------------------------------------------ */
__global__ __launch_bounds__(256) void sgemm128(const float* __restrict__ A,
                                                const float* __restrict__ B,
                                                float* __restrict__ C,
                                                int M, int N, int K) {
    __shared__ float As[8][128];
    __shared__ float Bs[8][128];
    int tid = threadIdx.x;
    int bm = blockIdx.y * 128;
    int bn = blockIdx.x * 128;
    int tr = (tid / 16) * 8;
    int tc = (tid % 16) * 8;

    float acc[8][8];
#pragma unroll
    for (int i = 0; i < 8; i++)
#pragma unroll
        for (int j = 0; j < 8; j++) acc[i][j] = 0.f;

    int aRow = tid / 2, aCol = (tid % 2) * 4;
    int bRow = tid / 32, bCol = (tid % 32) * 4;
    const float* Ap = A + (size_t)(bm + aRow) * K + aCol;
    const float* Bp = B + (size_t)bRow * N + bn + bCol;

    for (int k0 = 0; k0 < K; k0 += 8) {
        float4 av = *(const float4*)(Ap + k0);
        As[aCol + 0][aRow] = av.x;
        As[aCol + 1][aRow] = av.y;
        As[aCol + 2][aRow] = av.z;
        As[aCol + 3][aRow] = av.w;
        *(float4*)(&Bs[bRow][bCol]) = *(const float4*)(Bp + (size_t)k0 * N);
        __syncthreads();
#pragma unroll
        for (int kk = 0; kk < 8; kk++) {
            float a[8], b[8];
            *(float4*)(a)     = *(float4*)(&As[kk][tr]);
            *(float4*)(a + 4) = *(float4*)(&As[kk][tr + 4]);
            *(float4*)(b)     = *(float4*)(&Bs[kk][tc]);
            *(float4*)(b + 4) = *(float4*)(&Bs[kk][tc + 4]);
#pragma unroll
            for (int i = 0; i < 8; i++)
#pragma unroll
                for (int j = 0; j < 8; j++)
                    acc[i][j] += a[i] * b[j];
        }
        __syncthreads();
    }

#pragma unroll
    for (int i = 0; i < 8; i++) {
        float* cp = C + (size_t)(bm + tr + i) * N + bn + tc;
        *(float4*)(cp)     = *(float4*)(&acc[i][0]);
        *(float4*)(cp + 4) = *(float4*)(&acc[i][4]);
    }
}

/* ------------------------------------------------------------------ */
/* Flash-style attention. One CTA per (qblock of 64, head, batch).     */
/* 256 threads; thread (tr=tid/16, tc=tid%16) owns 4x4 microtile.      */
/* smem stride 68 floats (=17 float4, gcd(17,32)=1 -> conflict-free).  */
/* ------------------------------------------------------------------ */
#define SMS 68
#define ATTN_SMEM ((4*64*SMS)*4 + 64*4)

__global__ __launch_bounds__(256) void attn_kernel(const int* __restrict__ cu) {
    extern __shared__ float sm[];
    float* qs = sm;
    float* ks = sm + 64*SMS;
    float* vs = sm + 2*64*SMS;
    float* ps = sm + 3*64*SMS;
    int*  ksg = (int*)(sm + 4*64*SMS);

    int qb = blockIdx.x, h = blockIdx.y, b = blockIdx.z;
    int kvh = h >> 2;                       /* n_rep = 4 */
    int tid = threadIdx.x;
    int trg = tid >> 4;                     /* 0..15 */
    int tcg = tid & 15;
    int r0 = trg * 4, c0 = tcg * 4;

    int b0 = min(max(cu[b*4+0], 0), SEQ);
    int b1 = min(max(cu[b*4+1], 0), SEQ);
    int b2 = min(max(cu[b*4+2], 0), SEQ);
    int b3 = min(max(cu[b*4+3], 0), SEQ);

    float4* qs4 = (float4*)qs;
    float4* ks4 = (float4*)ks;
    float4* vs4 = (float4*)vs;
    float4* ps4 = (float4*)ps;

    /* load q tile, pre-scaled by 1/sqrt(d) */
    const float* qg = g_q + (size_t)(b*SEQ + qb*64) * QDIM + h*HD;
#pragma unroll
    for (int i = 0; i < 4; i++) {
        int f = tid + i * 256;
        int row = f >> 4, c4 = f & 15;
        float4 v = *(const float4*)(qg + (size_t)row * QDIM + c4*4);
        v.x *= 0.125f; v.y *= 0.125f; v.z *= 0.125f; v.w *= 0.125f;
        qs4[row*17 + c4] = v;
    }

    float m[4], l[4], o[4][4];
    int qp[4], qsg[4];
#pragma unroll
    for (int i = 0; i < 4; i++) {
        m[i] = -INFINITY; l[i] = 0.f;
        qp[i] = qb*64 + r0 + i;
        qsg[i] = (b0 <= qp[i]) + (b1 <= qp[i]) + (b2 <= qp[i]) + (b3 <= qp[i]);
#pragma unroll
        for (int j = 0; j < 4; j++) o[i][j] = 0.f;
    }

    const float* kg = g_k + (size_t)b*SEQ*KVDIM + kvh*HD;
    const float* vg = g_v + (size_t)b*SEQ*KVDIM + kvh*HD;

    for (int kb = 0; kb <= qb; kb++) {
        __syncthreads();   /* protect ks/vs/ps from previous iteration readers */
#pragma unroll
        for (int i = 0; i < 4; i++) {
            int f = tid + i * 256;
            int row = f >> 4, c4 = f & 15;
            size_t go = (size_t)(kb*64 + row) * KVDIM + c4*4;
            ks4[row*17 + c4] = *(const float4*)(kg + go);
            vs4[row*17 + c4] = *(const float4*)(vg + go);
        }
        if (tid < 64) {
            int kp = kb*64 + tid;
            ksg[tid] = (b0 <= kp) + (b1 <= kp) + (b2 <= kp) + (b3 <= kp);
        }
        __syncthreads();

        /* scores s = q @ k^T (already scaled) */
        float s[4][4];
#pragma unroll
        for (int i = 0; i < 4; i++)
#pragma unroll
            for (int j = 0; j < 4; j++) s[i][j] = 0.f;

#pragma unroll
        for (int d4 = 0; d4 < 16; d4++) {
            float4 qv[4], kv[4];
#pragma unroll
            for (int i = 0; i < 4; i++) qv[i] = qs4[(r0+i)*17 + d4];
#pragma unroll
            for (int j = 0; j < 4; j++) kv[j] = ks4[(c0+j)*17 + d4];
#pragma unroll
            for (int i = 0; i < 4; i++)
#pragma unroll
                for (int j = 0; j < 4; j++)
                    s[i][j] += qv[i].x*kv[j].x + qv[i].y*kv[j].y
                             + qv[i].z*kv[j].z + qv[i].w*kv[j].w;
        }

        /* mask: causal + same-segment */
#pragma unroll
        for (int j = 0; j < 4; j++) {
            int kp = kb*64 + c0 + j;
            int sk = ksg[c0 + j];
#pragma unroll
            for (int i = 0; i < 4; i++)
                if (kp > qp[i] || sk != qsg[i]) s[i][j] = -INFINITY;
        }

        /* online softmax */
        float mn[4], rs[4];
#pragma unroll
        for (int i = 0; i < 4; i++) {
            float rm = fmaxf(fmaxf(s[i][0], s[i][1]), fmaxf(s[i][2], s[i][3]));
#pragma unroll
            for (int off = 8; off >= 1; off >>= 1)
                rm = fmaxf(rm, __shfl_xor_sync(0xffffffffu, rm, off, 16));
            mn[i] = fmaxf(m[i], rm);
        }
#pragma unroll
        for (int i = 0; i < 4; i++) {
            rs[i] = 0.f;
            if (mn[i] > -INFINITY) {
#pragma unroll
                for (int j = 0; j < 4; j++) {
                    float p = __expf(s[i][j] - mn[i]);
                    s[i][j] = p;
                    rs[i] += p;
                }
            } else {
#pragma unroll
                for (int j = 0; j < 4; j++) s[i][j] = 0.f;
            }
#pragma unroll
            for (int off = 8; off >= 1; off >>= 1)
                rs[i] += __shfl_xor_sync(0xffffffffu, rs[i], off, 16);
        }
#pragma unroll
        for (int i = 0; i < 4; i++) {
            float sc = (m[i] > -INFINITY) ? __expf(m[i] - mn[i]) : 0.f;
            l[i] = l[i] * sc + rs[i];
            m[i] = mn[i];
#pragma unroll
            for (int j = 0; j < 4; j++) o[i][j] *= sc;
        }

        /* stage P */
#pragma unroll
        for (int i = 0; i < 4; i++)
            ps4[(r0+i)*17 + tcg] = make_float4(s[i][0], s[i][1], s[i][2], s[i][3]);
        __syncthreads();

        /* O += P @ V */
#pragma unroll
        for (int j4 = 0; j4 < 16; j4++) {
            float4 pv[4];
#pragma unroll
            for (int i = 0; i < 4; i++) pv[i] = ps4[(r0+i)*17 + j4];
#pragma unroll
            for (int jj = 0; jj < 4; jj++) {
                float4 vv = vs4[(j4*4 + jj)*17 + tcg];
#pragma unroll
                for (int i = 0; i < 4; i++) {
                    float p = ((const float*)&pv[i])[jj];
                    o[i][0] += p * vv.x;
                    o[i][1] += p * vv.y;
                    o[i][2] += p * vv.z;
                    o[i][3] += p * vv.w;
                }
            }
        }
    }

    /* epilogue: normalize and write */
    float* og = g_ao + (size_t)(b*SEQ + qb*64) * QDIM + h*HD + c0;
#pragma unroll
    for (int i = 0; i < 4; i++) {
        float inv = 1.f / l[i];
        float4 ov = make_float4(o[i][0]*inv, o[i][1]*inv, o[i][2]*inv, o[i][3]*inv);
        *(float4*)(og + (size_t)(r0+i) * QDIM) = ov;
    }
}

/* ------------------------------------------------------------------ */
extern "C" void kernel_launch(void* const* d_in, const int* in_sizes, int n_in,
                              void* d_out, int out_size) {
    const float* x  = (const float*)d_in[0];
    const int*   cu = (const int*)  d_in[1];
    const float* Wq = (const float*)d_in[2];
    const float* Wk = (const float*)d_in[3];
    const float* Wv = (const float*)d_in[4];
    const float* Wo = (const float*)d_in[5];
    float* out = (float*)d_out;

    float *q, *k, *v, *ao;
    cudaGetSymbolAddress((void**)&q,  g_q);
    cudaGetSymbolAddress((void**)&k,  g_k);
    cudaGetSymbolAddress((void**)&v,  g_v);
    cudaGetSymbolAddress((void**)&ao, g_ao);

    cudaFuncSetAttribute(attn_kernel,
                         cudaFuncAttributeMaxDynamicSharedMemorySize, ATTN_SMEM);

    /* QKV projections */
    sgemm128<<<dim3(QDIM /128, NTOK/128), 256>>>(x, Wq, q, NTOK, QDIM,  D_MODEL);
    sgemm128<<<dim3(KVDIM/128, NTOK/128), 256>>>(x, Wk, k, NTOK, KVDIM, D_MODEL);
    sgemm128<<<dim3(KVDIM/128, NTOK/128), 256>>>(x, Wv, v, NTOK, KVDIM, D_MODEL);

    /* RoPE */
    rope_table_kernel<<<(SEQ*(HD/2) + 255)/256, 256>>>();
    rope_apply_kernel<<<NTOK, 256>>>();

    /* attention */
    attn_kernel<<<dim3(SEQ/64, N_HEADS, BATCH), 256, ATTN_SMEM>>>(cu);

    /* output projection */
    sgemm128<<<dim3(D_MODEL/128, NTOK/128), 256>>>(ao, Wo, out, NTOK, D_MODEL, QDIM);
}

// round 3
// speedup vs baseline: 1.6300x; 1.6300x over previous
#include <cuda_runtime.h>
#include <cuda_bf16.h>
#include <math.h>
#include <stdint.h>

#define D_MODEL 2048
#define N_HEADS 32
#define N_KV    8
#define HD      64
#define SEQ     2048
#define BATCH   2
#define NTOK    (BATCH*SEQ)      /* 4096 */
#define QDIM    (N_HEADS*HD)     /* 2048 */
#define KVDIM   (N_KV*HD)        /* 512  */
#define ROPE_BASE 500000.0

/* ---------------- static device scratch (no allocations) ---------------- */
__device__ float g_q [NTOK*QDIM];
__device__ float g_k [NTOK*KVDIM];
__device__ float g_v [NTOK*KVDIM];
__device__ float g_ao[NTOK*QDIM];
__device__ float g_cos[SEQ*(HD/2)];
__device__ float g_sin[SEQ*(HD/2)];

__device__ __nv_bfloat16 g_xhi [NTOK*D_MODEL];
__device__ __nv_bfloat16 g_xlo [NTOK*D_MODEL];
__device__ __nv_bfloat16 g_wqhi[QDIM*D_MODEL];   /* [N,K] transposed */
__device__ __nv_bfloat16 g_wqlo[QDIM*D_MODEL];
__device__ __nv_bfloat16 g_wkhi[KVDIM*D_MODEL];
__device__ __nv_bfloat16 g_wklo[KVDIM*D_MODEL];
__device__ __nv_bfloat16 g_wvhi[KVDIM*D_MODEL];
__device__ __nv_bfloat16 g_wvlo[KVDIM*D_MODEL];
__device__ __nv_bfloat16 g_wohi[D_MODEL*QDIM];
__device__ __nv_bfloat16 g_wolo[D_MODEL*QDIM];
__device__ __nv_bfloat16 g_aohi[NTOK*QDIM];
__device__ __nv_bfloat16 g_aolo[NTOK*QDIM];

/* ---------------- PTX helpers (sm_80-era: valid on plain sm_103) -------- */
__device__ __forceinline__ uint32_t smem_u32(const void* p) {
    uint32_t a;
    asm("{ .reg .u64 t; cvta.to.shared.u64 t, %1; cvt.u32.u64 %0, t; }" : "=r"(a) : "l"(p));
    return a;
}
__device__ __forceinline__ void cp16(uint32_t saddr, const void* g) {
    asm volatile("cp.async.cg.shared.global [%0], [%1], 16;" :: "r"(saddr), "l"(g));
}
__device__ __forceinline__ void cp_commit() { asm volatile("cp.async.commit_group;" ::: "memory"); }
__device__ __forceinline__ void cp_wait0()  { asm volatile("cp.async.wait_group 0;"  ::: "memory"); }

__device__ __forceinline__ void ldmx4(uint32_t* r, uint32_t addr) {
    asm volatile("ldmatrix.sync.aligned.m8n8.x4.shared.b16 {%0,%1,%2,%3}, [%4];"
                 : "=r"(r[0]), "=r"(r[1]), "=r"(r[2]), "=r"(r[3]) : "r"(addr));
}
__device__ __forceinline__ void mma16816(float* d, const uint32_t* a, const uint32_t* b) {
    asm volatile(
        "mma.sync.aligned.m16n8k16.row.col.f32.bf16.bf16.f32 "
        "{%0,%1,%2,%3}, {%4,%5,%6,%7}, {%8,%9}, {%0,%1,%2,%3};"
        : "+f"(d[0]), "+f"(d[1]), "+f"(d[2]), "+f"(d[3])
        : "r"(a[0]), "r"(a[1]), "r"(a[2]), "r"(a[3]), "r"(b[0]), "r"(b[1]));
}

/* ---------------- split kernels ---------------- */
__global__ __launch_bounds__(256) void split_kernel(const float* __restrict__ src,
                                                    __nv_bfloat16* __restrict__ hi,
                                                    __nv_bfloat16* __restrict__ lo,
                                                    int n4) {
    int i = blockIdx.x * blockDim.x + threadIdx.x;
    if (i >= n4) return;
    float4 v = ((const float4*)src)[i];
    __nv_bfloat16 h[4], l[4];
    float vv[4] = {v.x, v.y, v.z, v.w};
#pragma unroll
    for (int j = 0; j < 4; j++) {
        h[j] = __float2bfloat16(vv[j]);
        l[j] = __float2bfloat16(vv[j] - __bfloat162float(h[j]));
    }
    ((uint2*)hi)[i] = *(uint2*)h;
    ((uint2*)lo)[i] = *(uint2*)l;
}

/* transpose + split: W[K,N] fp32 -> hi/lo [N,K] bf16 */
__global__ __launch_bounds__(256) void tsplit_kernel(const float* __restrict__ W,
                                                     __nv_bfloat16* __restrict__ hi,
                                                     __nv_bfloat16* __restrict__ lo,
                                                     int K, int N) {
    __shared__ float t[32][33];
    int n0 = blockIdx.x * 32, k0 = blockIdx.y * 32;
    int tx = threadIdx.x, ty = threadIdx.y;  /* block (32,8) */
#pragma unroll
    for (int i = 0; i < 32; i += 8)
        t[ty + i][tx] = W[(size_t)(k0 + ty + i) * N + n0 + tx];
    __syncthreads();
#pragma unroll
    for (int i = 0; i < 32; i += 8) {
        float v = t[tx][ty + i];
        __nv_bfloat16 h = __float2bfloat16(v);
        float r = v - __bfloat162float(h);
        size_t o = (size_t)(n0 + ty + i) * K + k0 + tx;
        hi[o] = h;
        lo[o] = __float2bfloat16(r);
    }
}

/* ---------------- bf16x3 HMMA GEMM ----------------
 * C[M,N] fp32 = (Ahi+Alo)[M,K] @ (Bhi+Blo)[N,K]^T  (dropping Alo*Blo)
 * CTA 128x128, BK=32, 256 threads (8 warps, 2x4 -> 64x32 warp tile).
 * Smem rows padded to 40 bf16 (80 B stride: conflict-free ldmatrix).
 * cp.async double-buffered.
 */
#define TILE_B   10240            /* 128*40*2 bytes */
#define STAGE_B  (4*TILE_B)       /* AH AL BH BL   */
#define GEMM_SMEM (2*STAGE_B)     /* 81920 bytes   */

__global__ __launch_bounds__(256)
void hmma_gemm(const __nv_bfloat16* __restrict__ Ahi, const __nv_bfloat16* __restrict__ Alo,
               const __nv_bfloat16* __restrict__ Bhi, const __nv_bfloat16* __restrict__ Blo,
               float* __restrict__ C, int M, int N, int K) {
    extern __shared__ char smem[];
    uint32_t sb = smem_u32(smem);
    int tid = threadIdx.x, lane = tid & 31, wid = tid >> 5;
    int wm = wid >> 2, wn = wid & 3;               /* 2 x 4 warp grid */
    int bm = blockIdx.y * 128, bn = blockIdx.x * 128;

    /* cp.async mapping: per tile, 512 uint4; thread t does rows t/4 and t/4+64 */
    int lr = tid >> 2;            /* 0..63 */
    int lc = tid & 3;             /* uint4 within row */
    const __nv_bfloat16* gA1 = Ahi + (size_t)(bm + lr) * K + lc * 8;
    const __nv_bfloat16* gA2 = Alo + (size_t)(bm + lr) * K + lc * 8;
    const __nv_bfloat16* gB1 = Bhi + (size_t)(bn + lr) * K + lc * 8;
    const __nv_bfloat16* gB2 = Blo + (size_t)(bn + lr) * K + lc * 8;
    size_t rstep = (size_t)64 * K;
    uint32_t soff = lr * 80 + lc * 16;             /* bytes within tile */

    /* ldmatrix per-lane offsets (elements) */
    uint32_t aOff = (wm * 64 + (lane & 15)) * 40 + ((lane >> 4) << 3);
    uint32_t bOff = (wn * 32 + (lane & 7) + ((lane >> 4) << 3)) * 40 + (lane & 8);

    float acc[4][4][4];
#pragma unroll
    for (int i = 0; i < 4; i++)
#pragma unroll
        for (int j = 0; j < 4; j++)
#pragma unroll
            for (int t = 0; t < 4; t++) acc[i][j][t] = 0.f;

    int nkt = K >> 5;

    /* prologue: load stage 0 */
    {
        uint32_t st = sb + soff;
        cp16(st,              gA1);            cp16(st + 80*64,              gA1 + rstep);
        cp16(st + TILE_B,     gA2);            cp16(st + TILE_B + 80*64,     gA2 + rstep);
        cp16(st + 2*TILE_B,   gB1);            cp16(st + 2*TILE_B + 80*64,   gB1 + rstep);
        cp16(st + 3*TILE_B,   gB2);            cp16(st + 3*TILE_B + 80*64,   gB2 + rstep);
    }
    cp_commit(); cp_wait0(); __syncthreads();

    for (int kt = 0; kt < nkt; kt++) {
        if (kt + 1 < nkt) {
            int k0 = (kt + 1) << 5;
            uint32_t st = sb + ((kt + 1) & 1) * STAGE_B + soff;
            cp16(st,              gA1 + k0);   cp16(st + 80*64,              gA1 + rstep + k0);
            cp16(st + TILE_B,     gA2 + k0);   cp16(st + TILE_B + 80*64,     gA2 + rstep + k0);
            cp16(st + 2*TILE_B,   gB1 + k0);   cp16(st + 2*TILE_B + 80*64,   gB1 + rstep + k0);
            cp16(st + 3*TILE_B,   gB2 + k0);   cp16(st + 3*TILE_B + 80*64,   gB2 + rstep + k0);
        }
        cp_commit();

        uint32_t base = sb + (kt & 1) * STAGE_B;
#pragma unroll
        for (int kb = 0; kb < 32; kb += 16) {
            uint32_t ah[4][4], al[4][4], bh[2][4], bl[2][4];
#pragma unroll
            for (int mt = 0; mt < 4; mt++) {
                uint32_t o = 2 * (aOff + mt * 640 + kb);
                ldmx4(ah[mt], base + o);
                ldmx4(al[mt], base + TILE_B + o);
            }
#pragma unroll
            for (int p = 0; p < 2; p++) {
                uint32_t o = 2 * (bOff + p * 640 + kb);
                ldmx4(bh[p], base + 2*TILE_B + o);
                ldmx4(bl[p], base + 3*TILE_B + o);
            }
#pragma unroll
            for (int mt = 0; mt < 4; mt++)
#pragma unroll
                for (int nt = 0; nt < 4; nt++) {
                    const uint32_t* fh = &bh[nt >> 1][(nt & 1) * 2];
                    const uint32_t* fl = &bl[nt >> 1][(nt & 1) * 2];
                    mma16816(acc[mt][nt], ah[mt], fh);
                    mma16816(acc[mt][nt], ah[mt], fl);
                    mma16816(acc[mt][nt], al[mt], fh);
                }
        }
        cp_wait0();
        __syncthreads();
    }

    /* epilogue */
    int er = lane >> 2, ec = (lane & 3) * 2;
#pragma unroll
    for (int mt = 0; mt < 4; mt++)
#pragma unroll
        for (int nt = 0; nt < 4; nt++) {
            int row = bm + wm * 64 + mt * 16 + er;
            int col = bn + wn * 32 + nt * 8 + ec;
            *(float2*)(C + (size_t)row * N + col) =
                make_float2(acc[mt][nt][0], acc[mt][nt][1]);
            *(float2*)(C + (size_t)(row + 8) * N + col) =
                make_float2(acc[mt][nt][2], acc[mt][nt][3]);
        }
}

/* ---------------- RoPE ---------------- */
__global__ void rope_table_kernel() {
    int i = blockIdx.x * blockDim.x + threadIdx.x;
    if (i >= SEQ * (HD/2)) return;
    int t = i / (HD/2);
    int j = i % (HD/2);
    double inv = pow((double)ROPE_BASE, -(double)(2*j) / (double)HD);
    double ang = (double)t * inv;
    g_cos[i] = (float)cos(ang);
    g_sin[i] = (float)sin(ang);
}

__global__ __launch_bounds__(256) void rope_apply_kernel() {
    int tok = blockIdx.x;
    int s   = tok & (SEQ - 1);
    for (int pi = threadIdx.x; pi < (N_HEADS + N_KV) * (HD/2); pi += 256) {
        int head = pi >> 5;
        int j    = pi & 31;
        float c  = g_cos[s*32 + j];
        float sn = g_sin[s*32 + j];
        float* buf; long base;
        if (head < N_HEADS) { buf = g_q; base = (long)tok*QDIM  + head*HD; }
        else                { buf = g_k; base = (long)tok*KVDIM + (head-N_HEADS)*HD; }
        float x1 = buf[base + j];
        float x2 = buf[base + j + 32];
        buf[base + j]      = x1*c - x2*sn;
        buf[base + j + 32] = x2*c + x1*sn;
    }
}

/* ---------------- flash attention (fp32 SIMT) ---------------- */
#define SMS 68
#define ATTN_SMEM ((4*64*SMS)*4 + 64*4)

__global__ __launch_bounds__(256) void attn_kernel(const int* __restrict__ cu) {
    extern __shared__ float sm[];
    float* qs = sm;
    float* ks = sm + 64*SMS;
    float* vs = sm + 2*64*SMS;
    float* ps = sm + 3*64*SMS;
    int*  ksg = (int*)(sm + 4*64*SMS);

    int qb = blockIdx.x, h = blockIdx.y, b = blockIdx.z;
    int kvh = h >> 2;
    int tid = threadIdx.x;
    int trg = tid >> 4;
    int tcg = tid & 15;
    int r0 = trg * 4, c0 = tcg * 4;

    int b0 = min(max(cu[b*4+0], 0), SEQ);
    int b1 = min(max(cu[b*4+1], 0), SEQ);
    int b2 = min(max(cu[b*4+2], 0), SEQ);
    int b3 = min(max(cu[b*4+3], 0), SEQ);

    float4* qs4 = (float4*)qs;
    float4* ks4 = (float4*)ks;
    float4* vs4 = (float4*)vs;
    float4* ps4 = (float4*)ps;

    const float* qg = g_q + (size_t)(b*SEQ + qb*64) * QDIM + h*HD;
#pragma unroll
    for (int i = 0; i < 4; i++) {
        int f = tid + i * 256;
        int row = f >> 4, c4 = f & 15;
        float4 v = *(const float4*)(qg + (size_t)row * QDIM + c4*4);
        v.x *= 0.125f; v.y *= 0.125f; v.z *= 0.125f; v.w *= 0.125f;
        qs4[row*17 + c4] = v;
    }

    float m[4], l[4], o[4][4];
    int qp[4], qsg[4];
#pragma unroll
    for (int i = 0; i < 4; i++) {
        m[i] = -INFINITY; l[i] = 0.f;
        qp[i] = qb*64 + r0 + i;
        qsg[i] = (b0 <= qp[i]) + (b1 <= qp[i]) + (b2 <= qp[i]) + (b3 <= qp[i]);
#pragma unroll
        for (int j = 0; j < 4; j++) o[i][j] = 0.f;
    }

    const float* kg = g_k + (size_t)b*SEQ*KVDIM + kvh*HD;
    const float* vg = g_v + (size_t)b*SEQ*KVDIM + kvh*HD;

    for (int kb = 0; kb <= qb; kb++) {
        __syncthreads();
#pragma unroll
        for (int i = 0; i < 4; i++) {
            int f = tid + i * 256;
            int row = f >> 4, c4 = f & 15;
            size_t go = (size_t)(kb*64 + row) * KVDIM + c4*4;
            ks4[row*17 + c4] = *(const float4*)(kg + go);
            vs4[row*17 + c4] = *(const float4*)(vg + go);
        }
        if (tid < 64) {
            int kp = kb*64 + tid;
            ksg[tid] = (b0 <= kp) + (b1 <= kp) + (b2 <= kp) + (b3 <= kp);
        }
        __syncthreads();

        float s[4][4];
#pragma unroll
        for (int i = 0; i < 4; i++)
#pragma unroll
            for (int j = 0; j < 4; j++) s[i][j] = 0.f;

#pragma unroll
        for (int d4 = 0; d4 < 16; d4++) {
            float4 qv[4], kv[4];
#pragma unroll
            for (int i = 0; i < 4; i++) qv[i] = qs4[(r0+i)*17 + d4];
#pragma unroll
            for (int j = 0; j < 4; j++) kv[j] = ks4[(c0+j)*17 + d4];
#pragma unroll
            for (int i = 0; i < 4; i++)
#pragma unroll
                for (int j = 0; j < 4; j++)
                    s[i][j] += qv[i].x*kv[j].x + qv[i].y*kv[j].y
                             + qv[i].z*kv[j].z + qv[i].w*kv[j].w;
        }

#pragma unroll
        for (int j = 0; j < 4; j++) {
            int kp = kb*64 + c0 + j;
            int sk = ksg[c0 + j];
#pragma unroll
            for (int i = 0; i < 4; i++)
                if (kp > qp[i] || sk != qsg[i]) s[i][j] = -INFINITY;
        }

        float mn[4], rs[4];
#pragma unroll
        for (int i = 0; i < 4; i++) {
            float rm = fmaxf(fmaxf(s[i][0], s[i][1]), fmaxf(s[i][2], s[i][3]));
#pragma unroll
            for (int off = 8; off >= 1; off >>= 1)
                rm = fmaxf(rm, __shfl_xor_sync(0xffffffffu, rm, off, 16));
            mn[i] = fmaxf(m[i], rm);
        }
#pragma unroll
        for (int i = 0; i < 4; i++) {
            rs[i] = 0.f;
            if (mn[i] > -INFINITY) {
#pragma unroll
                for (int j = 0; j < 4; j++) {
                    float p = __expf(s[i][j] - mn[i]);
                    s[i][j] = p;
                    rs[i] += p;
                }
            } else {
#pragma unroll
                for (int j = 0; j < 4; j++) s[i][j] = 0.f;
            }
#pragma unroll
            for (int off = 8; off >= 1; off >>= 1)
                rs[i] += __shfl_xor_sync(0xffffffffu, rs[i], off, 16);
        }
#pragma unroll
        for (int i = 0; i < 4; i++) {
            float sc = (m[i] > -INFINITY) ? __expf(m[i] - mn[i]) : 0.f;
            l[i] = l[i] * sc + rs[i];
            m[i] = mn[i];
#pragma unroll
            for (int j = 0; j < 4; j++) o[i][j] *= sc;
        }

#pragma unroll
        for (int i = 0; i < 4; i++)
            ps4[(r0+i)*17 + tcg] = make_float4(s[i][0], s[i][1], s[i][2], s[i][3]);
        __syncthreads();

#pragma unroll
        for (int j4 = 0; j4 < 16; j4++) {
            float4 pv[4];
#pragma unroll
            for (int i = 0; i < 4; i++) pv[i] = ps4[(r0+i)*17 + j4];
#pragma unroll
            for (int jj = 0; jj < 4; jj++) {
                float4 vv = vs4[(j4*4 + jj)*17 + tcg];
#pragma unroll
                for (int i = 0; i < 4; i++) {
                    float p = ((const float*)&pv[i])[jj];
                    o[i][0] += p * vv.x;
                    o[i][1] += p * vv.y;
                    o[i][2] += p * vv.z;
                    o[i][3] += p * vv.w;
                }
            }
        }
    }

    float* og = g_ao + (size_t)(b*SEQ + qb*64) * QDIM + h*HD + c0;
#pragma unroll
    for (int i = 0; i < 4; i++) {
        float inv = 1.f / l[i];
        float4 ov = make_float4(o[i][0]*inv, o[i][1]*inv, o[i][2]*inv, o[i][3]*inv);
        *(float4*)(og + (size_t)(r0+i) * QDIM) = ov;
    }
}

/* ------------------------------------------------------------------ */
extern "C" void kernel_launch(void* const* d_in, const int* in_sizes, int n_in,
                              void* d_out, int out_size) {
    const float* x  = (const float*)d_in[0];
    const int*   cu = (const int*)  d_in[1];
    const float* Wq = (const float*)d_in[2];
    const float* Wk = (const float*)d_in[3];
    const float* Wv = (const float*)d_in[4];
    const float* Wo = (const float*)d_in[5];
    float* out = (float*)d_out;

    float *q, *k, *v, *ao;
    __nv_bfloat16 *xhi, *xlo, *wqhi, *wqlo, *wkhi, *wklo, *wvhi, *wvlo, *wohi, *wolo, *aohi, *aolo;
    cudaGetSymbolAddress((void**)&q,  g_q);
    cudaGetSymbolAddress((void**)&k,  g_k);
    cudaGetSymbolAddress((void**)&v,  g_v);
    cudaGetSymbolAddress((void**)&ao, g_ao);
    cudaGetSymbolAddress((void**)&xhi, g_xhi);   cudaGetSymbolAddress((void**)&xlo, g_xlo);
    cudaGetSymbolAddress((void**)&wqhi, g_wqhi); cudaGetSymbolAddress((void**)&wqlo, g_wqlo);
    cudaGetSymbolAddress((void**)&wkhi, g_wkhi); cudaGetSymbolAddress((void**)&wklo, g_wklo);
    cudaGetSymbolAddress((void**)&wvhi, g_wvhi); cudaGetSymbolAddress((void**)&wvlo, g_wvlo);
    cudaGetSymbolAddress((void**)&wohi, g_wohi); cudaGetSymbolAddress((void**)&wolo, g_wolo);
    cudaGetSymbolAddress((void**)&aohi, g_aohi); cudaGetSymbolAddress((void**)&aolo, g_aolo);

    cudaFuncSetAttribute(attn_kernel,
                         cudaFuncAttributeMaxDynamicSharedMemorySize, ATTN_SMEM);
    cudaFuncSetAttribute(hmma_gemm,
                         cudaFuncAttributeMaxDynamicSharedMemorySize, GEMM_SMEM);

    /* split x, transpose+split weights */
    split_kernel<<<(NTOK*D_MODEL/4 + 255)/256, 256>>>(x, xhi, xlo, NTOK*D_MODEL/4);
    tsplit_kernel<<<dim3(QDIM /32, D_MODEL/32), dim3(32,8)>>>(Wq, wqhi, wqlo, D_MODEL, QDIM);
    tsplit_kernel<<<dim3(KVDIM/32, D_MODEL/32), dim3(32,8)>>>(Wk, wkhi, wklo, D_MODEL, KVDIM);
    tsplit_kernel<<<dim3(KVDIM/32, D_MODEL/32), dim3(32,8)>>>(Wv, wvhi, wvlo, D_MODEL, KVDIM);
    tsplit_kernel<<<dim3(D_MODEL/32, QDIM/32), dim3(32,8)>>>(Wo, wohi, wolo, QDIM, D_MODEL);

    /* QKV projections on HMMA */
    hmma_gemm<<<dim3(QDIM /128, NTOK/128), 256, GEMM_SMEM>>>(xhi, xlo, wqhi, wqlo, q, NTOK, QDIM,  D_MODEL);
    hmma_gemm<<<dim3(KVDIM/128, NTOK/128), 256, GEMM_SMEM>>>(xhi, xlo, wkhi, wklo, k, NTOK, KVDIM, D_MODEL);
    hmma_gemm<<<dim3(KVDIM/128, NTOK/128), 256, GEMM_SMEM>>>(xhi, xlo, wvhi, wvlo, v, NTOK, KVDIM, D_MODEL);

    /* RoPE */
    rope_table_kernel<<<(SEQ*(HD/2) + 255)/256, 256>>>();
    rope_apply_kernel<<<NTOK, 256>>>();

    /* attention */
    attn_kernel<<<dim3(SEQ/64, N_HEADS, BATCH), 256, ATTN_SMEM>>>(cu);

    /* output projection */
    split_kernel<<<(NTOK*QDIM/4 + 255)/256, 256>>>(ao, aohi, aolo, NTOK*QDIM/4);
    hmma_gemm<<<dim3(D_MODEL/128, NTOK/128), 256, GEMM_SMEM>>>(aohi, aolo, wohi, wolo, out, NTOK, D_MODEL, QDIM);
}

// round 4
// speedup vs baseline: 2.6472x; 1.6240x over previous
#include <cuda_runtime.h>
#include <cuda_bf16.h>
#include <math.h>
#include <stdint.h>

#define D_MODEL 2048
#define N_HEADS 32
#define N_KV    8
#define HD      64
#define SEQ     2048
#define BATCH   2
#define NTOK    (BATCH*SEQ)      /* 4096 */
#define QDIM    (N_HEADS*HD)     /* 2048 */
#define KVDIM   (N_KV*HD)        /* 512  */
#define ROPE_BASE 500000.0

/* ---------------- static device scratch (no allocations) ---------------- */
__device__ float g_q [NTOK*QDIM];
__device__ float g_k [NTOK*KVDIM];
__device__ float g_v [NTOK*KVDIM];
__device__ float g_cos[SEQ*(HD/2)];
__device__ float g_sin[SEQ*(HD/2)];

__device__ __nv_bfloat16 g_xhi [NTOK*D_MODEL];
__device__ __nv_bfloat16 g_xlo [NTOK*D_MODEL];
__device__ __nv_bfloat16 g_wqhi[QDIM*D_MODEL];   /* [N,K] transposed */
__device__ __nv_bfloat16 g_wqlo[QDIM*D_MODEL];
__device__ __nv_bfloat16 g_wkhi[KVDIM*D_MODEL];
__device__ __nv_bfloat16 g_wklo[KVDIM*D_MODEL];
__device__ __nv_bfloat16 g_wvhi[KVDIM*D_MODEL];
__device__ __nv_bfloat16 g_wvlo[KVDIM*D_MODEL];
__device__ __nv_bfloat16 g_wohi[D_MODEL*QDIM];
__device__ __nv_bfloat16 g_wolo[D_MODEL*QDIM];
__device__ __nv_bfloat16 g_aohi[NTOK*QDIM];
__device__ __nv_bfloat16 g_aolo[NTOK*QDIM];

/* ---------------- PTX helpers (sm_80-era: valid on plain sm_103) -------- */
__device__ __forceinline__ uint32_t smem_u32(const void* p) {
    uint32_t a;
    asm("{ .reg .u64 t; cvta.to.shared.u64 t, %1; cvt.u32.u64 %0, t; }" : "=r"(a) : "l"(p));
    return a;
}
__device__ __forceinline__ void cp16(uint32_t saddr, const void* g) {
    asm volatile("cp.async.cg.shared.global [%0], [%1], 16;" :: "r"(saddr), "l"(g));
}
__device__ __forceinline__ void cp_commit() { asm volatile("cp.async.commit_group;" ::: "memory"); }
__device__ __forceinline__ void cp_wait0()  { asm volatile("cp.async.wait_group 0;"  ::: "memory"); }

__device__ __forceinline__ void ldmx4(uint32_t* r, uint32_t addr) {
    asm volatile("ldmatrix.sync.aligned.m8n8.x4.shared.b16 {%0,%1,%2,%3}, [%4];"
                 : "=r"(r[0]), "=r"(r[1]), "=r"(r[2]), "=r"(r[3]) : "r"(addr));
}
__device__ __forceinline__ void mma16816(float* d, const uint32_t* a, const uint32_t* b) {
    asm volatile(
        "mma.sync.aligned.m16n8k16.row.col.f32.bf16.bf16.f32 "
        "{%0,%1,%2,%3}, {%4,%5,%6,%7}, {%8,%9}, {%0,%1,%2,%3};"
        : "+f"(d[0]), "+f"(d[1]), "+f"(d[2]), "+f"(d[3])
        : "r"(a[0]), "r"(a[1]), "r"(a[2]), "r"(a[3]), "r"(b[0]), "r"(b[1]));
}

/* ---------------- split kernels ---------------- */
__global__ __launch_bounds__(256) void split_kernel(const float* __restrict__ src,
                                                    __nv_bfloat16* __restrict__ hi,
                                                    __nv_bfloat16* __restrict__ lo,
                                                    int n4) {
    int i = blockIdx.x * blockDim.x + threadIdx.x;
    if (i >= n4) return;
    float4 v = ((const float4*)src)[i];
    __nv_bfloat16 h[4], l[4];
    float vv[4] = {v.x, v.y, v.z, v.w};
#pragma unroll
    for (int j = 0; j < 4; j++) {
        h[j] = __float2bfloat16(vv[j]);
        l[j] = __float2bfloat16(vv[j] - __bfloat162float(h[j]));
    }
    ((uint2*)hi)[i] = *(uint2*)h;
    ((uint2*)lo)[i] = *(uint2*)l;
}

/* transpose + split: W[K,N] fp32 -> hi/lo [N,K] bf16 */
__global__ __launch_bounds__(256) void tsplit_kernel(const float* __restrict__ W,
                                                     __nv_bfloat16* __restrict__ hi,
                                                     __nv_bfloat16* __restrict__ lo,
                                                     int K, int N) {
    __shared__ float t[32][33];
    int n0 = blockIdx.x * 32, k0 = blockIdx.y * 32;
    int tx = threadIdx.x, ty = threadIdx.y;  /* block (32,8) */
#pragma unroll
    for (int i = 0; i < 32; i += 8)
        t[ty + i][tx] = W[(size_t)(k0 + ty + i) * N + n0 + tx];
    __syncthreads();
#pragma unroll
    for (int i = 0; i < 32; i += 8) {
        float v = t[tx][ty + i];
        __nv_bfloat16 h = __float2bfloat16(v);
        float r = v - __bfloat162float(h);
        size_t o = (size_t)(n0 + ty + i) * K + k0 + tx;
        hi[o] = h;
        lo[o] = __float2bfloat16(r);
    }
}

/* ---------------- bf16x3 HMMA GEMM ---------------- */
#define TILE_B   10240            /* 128*40*2 bytes */
#define STAGE_B  (4*TILE_B)
#define GEMM_SMEM (2*STAGE_B)

__global__ __launch_bounds__(256)
void hmma_gemm(const __nv_bfloat16* __restrict__ Ahi, const __nv_bfloat16* __restrict__ Alo,
               const __nv_bfloat16* __restrict__ Bhi, const __nv_bfloat16* __restrict__ Blo,
               float* __restrict__ C, int M, int N, int K) {
    extern __shared__ char smem[];
    uint32_t sb = smem_u32(smem);
    int tid = threadIdx.x, lane = tid & 31, wid = tid >> 5;
    int wm = wid >> 2, wn = wid & 3;
    int bm = blockIdx.y * 128, bn = blockIdx.x * 128;

    int lr = tid >> 2;
    int lc = tid & 3;
    const __nv_bfloat16* gA1 = Ahi + (size_t)(bm + lr) * K + lc * 8;
    const __nv_bfloat16* gA2 = Alo + (size_t)(bm + lr) * K + lc * 8;
    const __nv_bfloat16* gB1 = Bhi + (size_t)(bn + lr) * K + lc * 8;
    const __nv_bfloat16* gB2 = Blo + (size_t)(bn + lr) * K + lc * 8;
    size_t rstep = (size_t)64 * K;
    uint32_t soff = lr * 80 + lc * 16;

    uint32_t aOff = (wm * 64 + (lane & 15)) * 40 + ((lane >> 4) << 3);
    uint32_t bOff = (wn * 32 + (lane & 7) + ((lane >> 4) << 3)) * 40 + (lane & 8);

    float acc[4][4][4];
#pragma unroll
    for (int i = 0; i < 4; i++)
#pragma unroll
        for (int j = 0; j < 4; j++)
#pragma unroll
            for (int t = 0; t < 4; t++) acc[i][j][t] = 0.f;

    int nkt = K >> 5;

    {
        uint32_t st = sb + soff;
        cp16(st,              gA1);            cp16(st + 80*64,              gA1 + rstep);
        cp16(st + TILE_B,     gA2);            cp16(st + TILE_B + 80*64,     gA2 + rstep);
        cp16(st + 2*TILE_B,   gB1);            cp16(st + 2*TILE_B + 80*64,   gB1 + rstep);
        cp16(st + 3*TILE_B,   gB2);            cp16(st + 3*TILE_B + 80*64,   gB2 + rstep);
    }
    cp_commit(); cp_wait0(); __syncthreads();

    for (int kt = 0; kt < nkt; kt++) {
        if (kt + 1 < nkt) {
            int k0 = (kt + 1) << 5;
            uint32_t st = sb + ((kt + 1) & 1) * STAGE_B + soff;
            cp16(st,              gA1 + k0);   cp16(st + 80*64,              gA1 + rstep + k0);
            cp16(st + TILE_B,     gA2 + k0);   cp16(st + TILE_B + 80*64,     gA2 + rstep + k0);
            cp16(st + 2*TILE_B,   gB1 + k0);   cp16(st + 2*TILE_B + 80*64,   gB1 + rstep + k0);
            cp16(st + 3*TILE_B,   gB2 + k0);   cp16(st + 3*TILE_B + 80*64,   gB2 + rstep + k0);
        }
        cp_commit();

        uint32_t base = sb + (kt & 1) * STAGE_B;
#pragma unroll
        for (int kb = 0; kb < 32; kb += 16) {
            uint32_t ah[4][4], al[4][4], bh[2][4], bl[2][4];
#pragma unroll
            for (int mt = 0; mt < 4; mt++) {
                uint32_t o = 2 * (aOff + mt * 640 + kb);
                ldmx4(ah[mt], base + o);
                ldmx4(al[mt], base + TILE_B + o);
            }
#pragma unroll
            for (int p = 0; p < 2; p++) {
                uint32_t o = 2 * (bOff + p * 640 + kb);
                ldmx4(bh[p], base + 2*TILE_B + o);
                ldmx4(bl[p], base + 3*TILE_B + o);
            }
#pragma unroll
            for (int mt = 0; mt < 4; mt++)
#pragma unroll
                for (int nt = 0; nt < 4; nt++) {
                    const uint32_t* fh = &bh[nt >> 1][(nt & 1) * 2];
                    const uint32_t* fl = &bl[nt >> 1][(nt & 1) * 2];
                    mma16816(acc[mt][nt], ah[mt], fh);
                    mma16816(acc[mt][nt], ah[mt], fl);
                    mma16816(acc[mt][nt], al[mt], fh);
                }
        }
        cp_wait0();
        __syncthreads();
    }

    int er = lane >> 2, ec = (lane & 3) * 2;
#pragma unroll
    for (int mt = 0; mt < 4; mt++)
#pragma unroll
        for (int nt = 0; nt < 4; nt++) {
            int row = bm + wm * 64 + mt * 16 + er;
            int col = bn + wn * 32 + nt * 8 + ec;
            *(float2*)(C + (size_t)row * N + col) =
                make_float2(acc[mt][nt][0], acc[mt][nt][1]);
            *(float2*)(C + (size_t)(row + 8) * N + col) =
                make_float2(acc[mt][nt][2], acc[mt][nt][3]);
        }
}

/* ---------------- RoPE ---------------- */
__global__ void rope_table_kernel() {
    int i = blockIdx.x * blockDim.x + threadIdx.x;
    if (i >= SEQ * (HD/2)) return;
    int t = i / (HD/2);
    int j = i % (HD/2);
    double inv = pow((double)ROPE_BASE, -(double)(2*j) / (double)HD);
    double ang = (double)t * inv;
    g_cos[i] = (float)cos(ang);
    g_sin[i] = (float)sin(ang);
}

__global__ __launch_bounds__(256) void rope_apply_kernel() {
    int tok = blockIdx.x;
    int s   = tok & (SEQ - 1);
    for (int pi = threadIdx.x; pi < (N_HEADS + N_KV) * (HD/2); pi += 256) {
        int head = pi >> 5;
        int j    = pi & 31;
        float c  = g_cos[s*32 + j];
        float sn = g_sin[s*32 + j];
        float* buf; long base;
        if (head < N_HEADS) { buf = g_q; base = (long)tok*QDIM  + head*HD; }
        else                { buf = g_k; base = (long)tok*KVDIM + (head-N_HEADS)*HD; }
        float x1 = buf[base + j];
        float x2 = buf[base + j + 32];
        buf[base + j]      = x1*c - x2*sn;
        buf[base + j + 32] = x2*c + x1*sn;
    }
}

/* ---------------- flash attention (fp32 SIMT + segment skip) ----------- */
#define SMS 68
#define ATTN_SMEM ((4*64*SMS)*4 + 64*4)

__global__ __launch_bounds__(256) void attn_kernel(const int* __restrict__ cu) {
    extern __shared__ float sm[];
    float* qs = sm;
    float* ks = sm + 64*SMS;
    float* vs = sm + 2*64*SMS;
    float* ps = sm + 3*64*SMS;
    int*  ksg = (int*)(sm + 4*64*SMS);

    int qb = blockIdx.x, h = blockIdx.y, b = blockIdx.z;
    int kvh = h >> 2;
    int tid = threadIdx.x;
    int trg = tid >> 4;
    int tcg = tid & 15;
    int r0 = trg * 4, c0 = tcg * 4;

    int b0 = min(max(cu[b*4+0], 0), SEQ);
    int b1 = min(max(cu[b*4+1], 0), SEQ);
    int b2 = min(max(cu[b*4+2], 0), SEQ);
    int b3 = min(max(cu[b*4+3], 0), SEQ);

    /* segment-skip: keys before the segment start of this block's first row
       are fully masked for every row in the block (causal + same-segment). */
    int p0 = qb * 64;
    int s_start = 0;
    if (b0 <= p0) s_start = b0;
    if (b1 <= p0) s_start = max(s_start, b1);
    if (b2 <= p0) s_start = max(s_start, b2);
    if (b3 <= p0) s_start = max(s_start, b3);
    int kb0 = s_start >> 6;

    float4* qs4 = (float4*)qs;
    float4* ks4 = (float4*)ks;
    float4* vs4 = (float4*)vs;
    float4* ps4 = (float4*)ps;

    const float* qg = g_q + (size_t)(b*SEQ + qb*64) * QDIM + h*HD;
#pragma unroll
    for (int i = 0; i < 4; i++) {
        int f = tid + i * 256;
        int row = f >> 4, c4 = f & 15;
        float4 v = *(const float4*)(qg + (size_t)row * QDIM + c4*4);
        v.x *= 0.125f; v.y *= 0.125f; v.z *= 0.125f; v.w *= 0.125f;
        qs4[row*17 + c4] = v;
    }

    float m[4], l[4], o[4][4];
    int qp[4], qsg[4];
#pragma unroll
    for (int i = 0; i < 4; i++) {
        m[i] = -INFINITY; l[i] = 0.f;
        qp[i] = qb*64 + r0 + i;
        qsg[i] = (b0 <= qp[i]) + (b1 <= qp[i]) + (b2 <= qp[i]) + (b3 <= qp[i]);
#pragma unroll
        for (int j = 0; j < 4; j++) o[i][j] = 0.f;
    }

    const float* kg = g_k + (size_t)b*SEQ*KVDIM + kvh*HD;
    const float* vg = g_v + (size_t)b*SEQ*KVDIM + kvh*HD;

    for (int kb = kb0; kb <= qb; kb++) {
        __syncthreads();
#pragma unroll
        for (int i = 0; i < 4; i++) {
            int f = tid + i * 256;
            int row = f >> 4, c4 = f & 15;
            size_t go = (size_t)(kb*64 + row) * KVDIM + c4*4;
            ks4[row*17 + c4] = *(const float4*)(kg + go);
            vs4[row*17 + c4] = *(const float4*)(vg + go);
        }
        if (tid < 64) {
            int kp = kb*64 + tid;
            ksg[tid] = (b0 <= kp) + (b1 <= kp) + (b2 <= kp) + (b3 <= kp);
        }
        __syncthreads();

        float s[4][4];
#pragma unroll
        for (int i = 0; i < 4; i++)
#pragma unroll
            for (int j = 0; j < 4; j++) s[i][j] = 0.f;

#pragma unroll
        for (int d4 = 0; d4 < 16; d4++) {
            float4 qv[4], kv[4];
#pragma unroll
            for (int i = 0; i < 4; i++) qv[i] = qs4[(r0+i)*17 + d4];
#pragma unroll
            for (int j = 0; j < 4; j++) kv[j] = ks4[(c0+j)*17 + d4];
#pragma unroll
            for (int i = 0; i < 4; i++)
#pragma unroll
                for (int j = 0; j < 4; j++)
                    s[i][j] += qv[i].x*kv[j].x + qv[i].y*kv[j].y
                             + qv[i].z*kv[j].z + qv[i].w*kv[j].w;
        }

#pragma unroll
        for (int j = 0; j < 4; j++) {
            int kp = kb*64 + c0 + j;
            int sk = ksg[c0 + j];
#pragma unroll
            for (int i = 0; i < 4; i++)
                if (kp > qp[i] || sk != qsg[i]) s[i][j] = -INFINITY;
        }

        float mn[4], rs[4];
#pragma unroll
        for (int i = 0; i < 4; i++) {
            float rm = fmaxf(fmaxf(s[i][0], s[i][1]), fmaxf(s[i][2], s[i][3]));
#pragma unroll
            for (int off = 8; off >= 1; off >>= 1)
                rm = fmaxf(rm, __shfl_xor_sync(0xffffffffu, rm, off, 16));
            mn[i] = fmaxf(m[i], rm);
        }
#pragma unroll
        for (int i = 0; i < 4; i++) {
            rs[i] = 0.f;
            if (mn[i] > -INFINITY) {
#pragma unroll
                for (int j = 0; j < 4; j++) {
                    float p = __expf(s[i][j] - mn[i]);
                    s[i][j] = p;
                    rs[i] += p;
                }
            } else {
#pragma unroll
                for (int j = 0; j < 4; j++) s[i][j] = 0.f;
            }
#pragma unroll
            for (int off = 8; off >= 1; off >>= 1)
                rs[i] += __shfl_xor_sync(0xffffffffu, rs[i], off, 16);
        }
#pragma unroll
        for (int i = 0; i < 4; i++) {
            float sc = (m[i] > -INFINITY) ? __expf(m[i] - mn[i]) : 0.f;
            l[i] = l[i] * sc + rs[i];
            m[i] = mn[i];
#pragma unroll
            for (int j = 0; j < 4; j++) o[i][j] *= sc;
        }

#pragma unroll
        for (int i = 0; i < 4; i++)
            ps4[(r0+i)*17 + tcg] = make_float4(s[i][0], s[i][1], s[i][2], s[i][3]);
        __syncthreads();

#pragma unroll
        for (int j4 = 0; j4 < 16; j4++) {
            float4 pv[4];
#pragma unroll
            for (int i = 0; i < 4; i++) pv[i] = ps4[(r0+i)*17 + j4];
#pragma unroll
            for (int jj = 0; jj < 4; jj++) {
                float4 vv = vs4[(j4*4 + jj)*17 + tcg];
#pragma unroll
                for (int i = 0; i < 4; i++) {
                    float p = ((const float*)&pv[i])[jj];
                    o[i][0] += p * vv.x;
                    o[i][1] += p * vv.y;
                    o[i][2] += p * vv.z;
                    o[i][3] += p * vv.w;
                }
            }
        }
    }

    /* epilogue: normalize and write hi/lo bf16 split directly */
    size_t obase = (size_t)(b*SEQ + qb*64) * QDIM + h*HD + c0;
#pragma unroll
    for (int i = 0; i < 4; i++) {
        float inv = 1.f / l[i];
        __nv_bfloat16 hv[4], lv[4];
#pragma unroll
        for (int j = 0; j < 4; j++) {
            float val = o[i][j] * inv;
            hv[j] = __float2bfloat16(val);
            lv[j] = __float2bfloat16(val - __bfloat162float(hv[j]));
        }
        size_t oo = obase + (size_t)(r0+i) * QDIM;
        *(uint2*)(g_aohi + oo) = *(uint2*)hv;
        *(uint2*)(g_aolo + oo) = *(uint2*)lv;
    }
}

/* ------------------------------------------------------------------ */
extern "C" void kernel_launch(void* const* d_in, const int* in_sizes, int n_in,
                              void* d_out, int out_size) {
    const float* x  = (const float*)d_in[0];
    const int*   cu = (const int*)  d_in[1];
    const float* Wq = (const float*)d_in[2];
    const float* Wk = (const float*)d_in[3];
    const float* Wv = (const float*)d_in[4];
    const float* Wo = (const float*)d_in[5];
    float* out = (float*)d_out;

    float *q, *k, *v;
    __nv_bfloat16 *xhi, *xlo, *wqhi, *wqlo, *wkhi, *wklo, *wvhi, *wvlo, *wohi, *wolo, *aohi, *aolo;
    cudaGetSymbolAddress((void**)&q,  g_q);
    cudaGetSymbolAddress((void**)&k,  g_k);
    cudaGetSymbolAddress((void**)&v,  g_v);
    cudaGetSymbolAddress((void**)&xhi, g_xhi);   cudaGetSymbolAddress((void**)&xlo, g_xlo);
    cudaGetSymbolAddress((void**)&wqhi, g_wqhi); cudaGetSymbolAddress((void**)&wqlo, g_wqlo);
    cudaGetSymbolAddress((void**)&wkhi, g_wkhi); cudaGetSymbolAddress((void**)&wklo, g_wklo);
    cudaGetSymbolAddress((void**)&wvhi, g_wvhi); cudaGetSymbolAddress((void**)&wvlo, g_wvlo);
    cudaGetSymbolAddress((void**)&wohi, g_wohi); cudaGetSymbolAddress((void**)&wolo, g_wolo);
    cudaGetSymbolAddress((void**)&aohi, g_aohi); cudaGetSymbolAddress((void**)&aolo, g_aolo);

    cudaFuncSetAttribute(attn_kernel,
                         cudaFuncAttributeMaxDynamicSharedMemorySize, ATTN_SMEM);
    cudaFuncSetAttribute(hmma_gemm,
                         cudaFuncAttributeMaxDynamicSharedMemorySize, GEMM_SMEM);

    /* split x, transpose+split weights */
    split_kernel<<<(NTOK*D_MODEL/4 + 255)/256, 256>>>(x, xhi, xlo, NTOK*D_MODEL/4);
    tsplit_kernel<<<dim3(QDIM /32, D_MODEL/32), dim3(32,8)>>>(Wq, wqhi, wqlo, D_MODEL, QDIM);
    tsplit_kernel<<<dim3(KVDIM/32, D_MODEL/32), dim3(32,8)>>>(Wk, wkhi, wklo, D_MODEL, KVDIM);
    tsplit_kernel<<<dim3(KVDIM/32, D_MODEL/32), dim3(32,8)>>>(Wv, wvhi, wvlo, D_MODEL, KVDIM);
    tsplit_kernel<<<dim3(D_MODEL/32, QDIM/32), dim3(32,8)>>>(Wo, wohi, wolo, QDIM, D_MODEL);

    /* QKV projections on HMMA */
    hmma_gemm<<<dim3(QDIM /128, NTOK/128), 256, GEMM_SMEM>>>(xhi, xlo, wqhi, wqlo, q, NTOK, QDIM,  D_MODEL);
    hmma_gemm<<<dim3(KVDIM/128, NTOK/128), 256, GEMM_SMEM>>>(xhi, xlo, wkhi, wklo, k, NTOK, KVDIM, D_MODEL);
    hmma_gemm<<<dim3(KVDIM/128, NTOK/128), 256, GEMM_SMEM>>>(xhi, xlo, wvhi, wvlo, v, NTOK, KVDIM, D_MODEL);

    /* RoPE */
    rope_table_kernel<<<(SEQ*(HD/2) + 255)/256, 256>>>();
    rope_apply_kernel<<<NTOK, 256>>>();

    /* attention (writes bf16 hi/lo splits directly) */
    attn_kernel<<<dim3(SEQ/64, N_HEADS, BATCH), 256, ATTN_SMEM>>>(cu);

    /* output projection */
    hmma_gemm<<<dim3(D_MODEL/128, NTOK/128), 256, GEMM_SMEM>>>(aohi, aolo, wohi, wolo, out, NTOK, D_MODEL, QDIM);
}

// round 5
// speedup vs baseline: 4.0069x; 1.5137x over previous
#include <cuda_runtime.h>
#include <cuda_bf16.h>
#include <math.h>
#include <stdint.h>

#define D_MODEL 2048
#define N_HEADS 32
#define N_KV    8
#define HD      64
#define SEQ     2048
#define BATCH   2
#define NTOK    (BATCH*SEQ)      /* 4096 */
#define QDIM    (N_HEADS*HD)     /* 2048 */
#define KVDIM   (N_KV*HD)        /* 512  */
#define ROPE_BASE 500000.0
#define SCALE_L2E 0.1803368801111204f   /* 0.125 * log2(e) */

/* ---------------- static device scratch (no allocations) ---------------- */
__device__ float g_q [NTOK*QDIM];
__device__ float g_k [NTOK*KVDIM];
__device__ float g_v [NTOK*KVDIM];
__device__ float g_cos[SEQ*(HD/2)];
__device__ float g_sin[SEQ*(HD/2)];

__device__ __nv_bfloat16 g_xhi [NTOK*D_MODEL];
__device__ __nv_bfloat16 g_xlo [NTOK*D_MODEL];
__device__ __nv_bfloat16 g_wqhi[QDIM*D_MODEL];
__device__ __nv_bfloat16 g_wqlo[QDIM*D_MODEL];
__device__ __nv_bfloat16 g_wkhi[KVDIM*D_MODEL];
__device__ __nv_bfloat16 g_wklo[KVDIM*D_MODEL];
__device__ __nv_bfloat16 g_wvhi[KVDIM*D_MODEL];
__device__ __nv_bfloat16 g_wvlo[KVDIM*D_MODEL];
__device__ __nv_bfloat16 g_wohi[D_MODEL*QDIM];
__device__ __nv_bfloat16 g_wolo[D_MODEL*QDIM];
__device__ __nv_bfloat16 g_aohi[NTOK*QDIM];
__device__ __nv_bfloat16 g_aolo[NTOK*QDIM];

/* attention operands, pre-split (rope-rotated; q pre-scaled by 0.125*log2e) */
__device__ __nv_bfloat16 g_qhi[NTOK*QDIM];
__device__ __nv_bfloat16 g_qlo[NTOK*QDIM];
__device__ __nv_bfloat16 g_khi[NTOK*KVDIM];
__device__ __nv_bfloat16 g_klo[NTOK*KVDIM];
__device__ __nv_bfloat16 g_vhi[NTOK*KVDIM];
__device__ __nv_bfloat16 g_vlo[NTOK*KVDIM];

/* ---------------- PTX helpers ---------------- */
__device__ __forceinline__ uint32_t smem_u32(const void* p) {
    uint32_t a;
    asm("{ .reg .u64 t; cvta.to.shared.u64 t, %1; cvt.u32.u64 %0, t; }" : "=r"(a) : "l"(p));
    return a;
}
__device__ __forceinline__ void cp16(uint32_t saddr, const void* g) {
    asm volatile("cp.async.cg.shared.global [%0], [%1], 16;" :: "r"(saddr), "l"(g));
}
__device__ __forceinline__ void cp_commit() { asm volatile("cp.async.commit_group;" ::: "memory"); }
__device__ __forceinline__ void cp_wait0()  { asm volatile("cp.async.wait_group 0;"  ::: "memory"); }

__device__ __forceinline__ void ldmx4(uint32_t* r, uint32_t addr) {
    asm volatile("ldmatrix.sync.aligned.m8n8.x4.shared.b16 {%0,%1,%2,%3}, [%4];"
                 : "=r"(r[0]), "=r"(r[1]), "=r"(r[2]), "=r"(r[3]) : "r"(addr));
}
__device__ __forceinline__ void ldmx4t(uint32_t* r, uint32_t addr) {
    asm volatile("ldmatrix.sync.aligned.m8n8.x4.trans.shared.b16 {%0,%1,%2,%3}, [%4];"
                 : "=r"(r[0]), "=r"(r[1]), "=r"(r[2]), "=r"(r[3]) : "r"(addr));
}
__device__ __forceinline__ void mma16816(float* d, const uint32_t* a, const uint32_t* b) {
    asm volatile(
        "mma.sync.aligned.m16n8k16.row.col.f32.bf16.bf16.f32 "
        "{%0,%1,%2,%3}, {%4,%5,%6,%7}, {%8,%9}, {%0,%1,%2,%3};"
        : "+f"(d[0]), "+f"(d[1]), "+f"(d[2]), "+f"(d[3])
        : "r"(a[0]), "r"(a[1]), "r"(a[2]), "r"(a[3]), "r"(b[0]), "r"(b[1]));
}
__device__ __forceinline__ float ex2(float x) {
    float y; asm("ex2.approx.f32 %0, %1;" : "=f"(y) : "f"(x)); return y;
}
__device__ __forceinline__ uint32_t pk(float a, float b) {
    __nv_bfloat162 t = __float22bfloat162_rn(make_float2(a, b));
    return *(uint32_t*)&t;
}

/* ---------------- split kernels ---------------- */
__global__ __launch_bounds__(256) void split_kernel(const float* __restrict__ src,
                                                    __nv_bfloat16* __restrict__ hi,
                                                    __nv_bfloat16* __restrict__ lo,
                                                    int n4) {
    int i = blockIdx.x * blockDim.x + threadIdx.x;
    if (i >= n4) return;
    float4 v = ((const float4*)src)[i];
    __nv_bfloat16 h[4], l[4];
    float vv[4] = {v.x, v.y, v.z, v.w};
#pragma unroll
    for (int j = 0; j < 4; j++) {
        h[j] = __float2bfloat16(vv[j]);
        l[j] = __float2bfloat16(vv[j] - __bfloat162float(h[j]));
    }
    ((uint2*)hi)[i] = *(uint2*)h;
    ((uint2*)lo)[i] = *(uint2*)l;
}

__global__ __launch_bounds__(256) void tsplit_kernel(const float* __restrict__ W,
                                                     __nv_bfloat16* __restrict__ hi,
                                                     __nv_bfloat16* __restrict__ lo,
                                                     int K, int N) {
    __shared__ float t[32][33];
    int n0 = blockIdx.x * 32, k0 = blockIdx.y * 32;
    int tx = threadIdx.x, ty = threadIdx.y;
#pragma unroll
    for (int i = 0; i < 32; i += 8)
        t[ty + i][tx] = W[(size_t)(k0 + ty + i) * N + n0 + tx];
    __syncthreads();
#pragma unroll
    for (int i = 0; i < 32; i += 8) {
        float v = t[tx][ty + i];
        __nv_bfloat16 h = __float2bfloat16(v);
        float r = v - __bfloat162float(h);
        size_t o = (size_t)(n0 + ty + i) * K + k0 + tx;
        hi[o] = h;
        lo[o] = __float2bfloat16(r);
    }
}

/* ---------------- bf16x3 HMMA GEMM (unchanged from R3) ---------------- */
#define TILE_B   10240
#define STAGE_B  (4*TILE_B)
#define GEMM_SMEM (2*STAGE_B)

__global__ __launch_bounds__(256)
void hmma_gemm(const __nv_bfloat16* __restrict__ Ahi, const __nv_bfloat16* __restrict__ Alo,
               const __nv_bfloat16* __restrict__ Bhi, const __nv_bfloat16* __restrict__ Blo,
               float* __restrict__ C, int M, int N, int K) {
    extern __shared__ char smem[];
    uint32_t sb = smem_u32(smem);
    int tid = threadIdx.x, lane = tid & 31, wid = tid >> 5;
    int wm = wid >> 2, wn = wid & 3;
    int bm = blockIdx.y * 128, bn = blockIdx.x * 128;

    int lr = tid >> 2;
    int lc = tid & 3;
    const __nv_bfloat16* gA1 = Ahi + (size_t)(bm + lr) * K + lc * 8;
    const __nv_bfloat16* gA2 = Alo + (size_t)(bm + lr) * K + lc * 8;
    const __nv_bfloat16* gB1 = Bhi + (size_t)(bn + lr) * K + lc * 8;
    const __nv_bfloat16* gB2 = Blo + (size_t)(bn + lr) * K + lc * 8;
    size_t rstep = (size_t)64 * K;
    uint32_t soff = lr * 80 + lc * 16;

    uint32_t aOff = (wm * 64 + (lane & 15)) * 40 + ((lane >> 4) << 3);
    uint32_t bOff = (wn * 32 + (lane & 7) + ((lane >> 4) << 3)) * 40 + (lane & 8);

    float acc[4][4][4];
#pragma unroll
    for (int i = 0; i < 4; i++)
#pragma unroll
        for (int j = 0; j < 4; j++)
#pragma unroll
            for (int t = 0; t < 4; t++) acc[i][j][t] = 0.f;

    int nkt = K >> 5;

    {
        uint32_t st = sb + soff;
        cp16(st,              gA1);            cp16(st + 80*64,              gA1 + rstep);
        cp16(st + TILE_B,     gA2);            cp16(st + TILE_B + 80*64,     gA2 + rstep);
        cp16(st + 2*TILE_B,   gB1);            cp16(st + 2*TILE_B + 80*64,   gB1 + rstep);
        cp16(st + 3*TILE_B,   gB2);            cp16(st + 3*TILE_B + 80*64,   gB2 + rstep);
    }
    cp_commit(); cp_wait0(); __syncthreads();

    for (int kt = 0; kt < nkt; kt++) {
        if (kt + 1 < nkt) {
            int k0 = (kt + 1) << 5;
            uint32_t st = sb + ((kt + 1) & 1) * STAGE_B + soff;
            cp16(st,              gA1 + k0);   cp16(st + 80*64,              gA1 + rstep + k0);
            cp16(st + TILE_B,     gA2 + k0);   cp16(st + TILE_B + 80*64,     gA2 + rstep + k0);
            cp16(st + 2*TILE_B,   gB1 + k0);   cp16(st + 2*TILE_B + 80*64,   gB1 + rstep + k0);
            cp16(st + 3*TILE_B,   gB2 + k0);   cp16(st + 3*TILE_B + 80*64,   gB2 + rstep + k0);
        }
        cp_commit();

        uint32_t base = sb + (kt & 1) * STAGE_B;
#pragma unroll
        for (int kb = 0; kb < 32; kb += 16) {
            uint32_t ah[4][4], al[4][4], bh[2][4], bl[2][4];
#pragma unroll
            for (int mt = 0; mt < 4; mt++) {
                uint32_t o = 2 * (aOff + mt * 640 + kb);
                ldmx4(ah[mt], base + o);
                ldmx4(al[mt], base + TILE_B + o);
            }
#pragma unroll
            for (int p = 0; p < 2; p++) {
                uint32_t o = 2 * (bOff + p * 640 + kb);
                ldmx4(bh[p], base + 2*TILE_B + o);
                ldmx4(bl[p], base + 3*TILE_B + o);
            }
#pragma unroll
            for (int mt = 0; mt < 4; mt++)
#pragma unroll
                for (int nt = 0; nt < 4; nt++) {
                    const uint32_t* fh = &bh[nt >> 1][(nt & 1) * 2];
                    const uint32_t* fl = &bl[nt >> 1][(nt & 1) * 2];
                    mma16816(acc[mt][nt], ah[mt], fh);
                    mma16816(acc[mt][nt], ah[mt], fl);
                    mma16816(acc[mt][nt], al[mt], fh);
                }
        }
        cp_wait0();
        __syncthreads();
    }

    int er = lane >> 2, ec = (lane & 3) * 2;
#pragma unroll
    for (int mt = 0; mt < 4; mt++)
#pragma unroll
        for (int nt = 0; nt < 4; nt++) {
            int row = bm + wm * 64 + mt * 16 + er;
            int col = bn + wn * 32 + nt * 8 + ec;
            *(float2*)(C + (size_t)row * N + col) =
                make_float2(acc[mt][nt][0], acc[mt][nt][1]);
            *(float2*)(C + (size_t)(row + 8) * N + col) =
                make_float2(acc[mt][nt][2], acc[mt][nt][3]);
        }
}

/* ---------------- RoPE ---------------- */
__global__ void rope_table_kernel() {
    int i = blockIdx.x * blockDim.x + threadIdx.x;
    if (i >= SEQ * (HD/2)) return;
    int t = i / (HD/2);
    int j = i % (HD/2);
    double inv = pow((double)ROPE_BASE, -(double)(2*j) / (double)HD);
    double ang = (double)t * inv;
    g_cos[i] = (float)cos(ang);
    g_sin[i] = (float)sin(ang);
}

/* rotate + (scale for q) + bf16 hi/lo split */
__global__ __launch_bounds__(256) void rope_split_kernel() {
    int tok = blockIdx.x;
    int s   = tok & (SEQ - 1);
    for (int pi = threadIdx.x; pi < (N_HEADS + N_KV) * (HD/2); pi += 256) {
        int head = pi >> 5;
        int j    = pi & 31;
        float c  = g_cos[s*32 + j];
        float sn = g_sin[s*32 + j];
        const float* buf;
        __nv_bfloat16 *hi, *lo;
        long base;
        float sc;
        if (head < N_HEADS) {
            buf = g_q; hi = g_qhi; lo = g_qlo;
            base = (long)tok*QDIM + head*HD;
            sc = SCALE_L2E;
        } else {
            buf = g_k; hi = g_khi; lo = g_klo;
            base = (long)tok*KVDIM + (head-N_HEADS)*HD;
            sc = 1.f;
        }
        float x1 = buf[base + j];
        float x2 = buf[base + j + 32];
        float r1 = (x1*c - x2*sn) * sc;
        float r2 = (x2*c + x1*sn) * sc;
        __nv_bfloat16 h1 = __float2bfloat16(r1);
        __nv_bfloat16 h2 = __float2bfloat16(r2);
        hi[base + j]      = h1;
        hi[base + j + 32] = h2;
        lo[base + j]      = __float2bfloat16(r1 - __bfloat162float(h1));
        lo[base + j + 32] = __float2bfloat16(r2 - __bfloat162float(h2));
    }
}

/* ---------------- HMMA flash attention ----------------
 * q-block 64, kv-block 64. 8 warps: wq = wid&3 (16 q rows), wk = wid>>2
 * (kv half of 32). Scores/PV in split-bf16 mma.sync, fp32 accum.
 * smem stage: KH|KL|VH|VL, each 64 rows x 144B (72 bf16, padded).
 */
#define AS_KH 0
#define AS_KL 9216
#define AS_VH 18432
#define AS_VL 27648
#define ATTN_SMEM 36864

__global__ __launch_bounds__(256)
void attn_kernel(const int* __restrict__ cu) {
    extern __shared__ char smem[];
    uint32_t sb = smem_u32(smem);
    int qb = blockIdx.x, h = blockIdx.y, b = blockIdx.z;
    int kvh = h >> 2;
    int tid = threadIdx.x, lane = tid & 31, wid = tid >> 5;
    int wq = wid & 3, wk = wid >> 2;

    int b0 = min(max(cu[b*4+0], 0), SEQ);
    int b1 = min(max(cu[b*4+1], 0), SEQ);
    int b2 = min(max(cu[b*4+2], 0), SEQ);
    int b3 = min(max(cu[b*4+3], 0), SEQ);

    int p0 = qb * 64;
    int s_start = 0;
    if (b0 <= p0) s_start = b0;
    if (b1 <= p0) s_start = max(s_start, b1);
    if (b2 <= p0) s_start = max(s_start, b2);
    if (b3 <= p0) s_start = max(s_start, b3);
    int kb0 = s_start >> 6;

    /* stage Q tile (hi/lo) into smem [rows 64 x 144B each] */
#pragma unroll
    for (int i = 0; i < 4; i++) {
        int arr = i >> 1;
        int rem = tid + (i & 1) * 256;
        int row = rem >> 3, c = rem & 7;
        const __nv_bfloat16* src = arr ? g_qlo : g_qhi;
        cp16(sb + arr*9216 + row*144 + c*16,
             src + (size_t)(b*SEQ + p0 + row) * QDIM + h*HD + c*8);
    }
    cp_commit(); cp_wait0(); __syncthreads();

    /* Q fragments: warp rows 16*wq..+15, 4 k-tiles over d */
    uint32_t qh[4][4], ql[4][4];
#pragma unroll
    for (int kt = 0; kt < 4; kt++) {
        uint32_t off = (uint32_t)(wq*16 + (lane & 15)) * 144 + (kt*16 + ((lane >> 4) << 3)) * 2;
        ldmx4(qh[kt], sb + off);
        ldmx4(ql[kt], sb + 9216 + off);
    }

    int qp0 = p0 + wq*16 + (lane >> 2);
    int qp1 = qp0 + 8;
    int qsg0 = (b0 <= qp0) + (b1 <= qp0) + (b2 <= qp0) + (b3 <= qp0);
    int qsg1 = (b0 <= qp1) + (b1 <= qp1) + (b2 <= qp1) + (b3 <= qp1);

    float m0 = -INFINITY, m1 = -INFINITY, l0 = 0.f, l1 = 0.f;
    float o[8][4];
#pragma unroll
    for (int nd = 0; nd < 8; nd++)
#pragma unroll
        for (int j = 0; j < 4; j++) o[nd][j] = 0.f;

    int colb = wk*32 + (lane & 3)*2;

    for (int kb = kb0; kb <= qb; kb++) {
        __syncthreads();   /* previous stage fully consumed */
#pragma unroll
        for (int i = 0; i < 8; i++) {
            int arr = i >> 1;
            int rem = tid + (i & 1) * 256;
            int row = rem >> 3, c = rem & 7;
            const __nv_bfloat16* src = (arr == 0) ? g_khi : (arr == 1) ? g_klo
                                     : (arr == 2) ? g_vhi : g_vlo;
            cp16(sb + arr*9216 + row*144 + c*16,
                 src + (size_t)(b*SEQ + kb*64 + row) * KVDIM + kvh*HD + c*8);
        }
        cp_commit(); cp_wait0(); __syncthreads();

        /* ---- scores: S = Q K^T (split 3-term) ---- */
        float s[4][4];
#pragma unroll
        for (int nt = 0; nt < 4; nt++)
#pragma unroll
            for (int j = 0; j < 4; j++) s[nt][j] = 0.f;

#pragma unroll
        for (int kt = 0; kt < 4; kt++) {
            uint32_t khf[2][4], klf[2][4];
#pragma unroll
            for (int np = 0; np < 2; np++) {
                int mq = lane >> 3, r = lane & 7;
                uint32_t off = (uint32_t)(wk*32 + np*16 + ((mq & 2) ? 8 : 0) + r) * 144
                             + (kt*16 + ((mq & 1) ? 8 : 0)) * 2;
                ldmx4(khf[np], sb + AS_KH + off);
                ldmx4(klf[np], sb + AS_KL + off);
            }
#pragma unroll
            for (int nt = 0; nt < 4; nt++) {
                const uint32_t* fh = &khf[nt >> 1][(nt & 1) * 2];
                const uint32_t* fl = &klf[nt >> 1][(nt & 1) * 2];
                mma16816(s[nt], qh[kt], fh);
                mma16816(s[nt], qh[kt], fl);
                mma16816(s[nt], ql[kt], fh);
            }
        }

        /* ---- mask ---- */
#pragma unroll
        for (int nt = 0; nt < 4; nt++)
#pragma unroll
            for (int e = 0; e < 2; e++) {
                int kp = kb*64 + colb + nt*8 + e;
                int sk = (b0 <= kp) + (b1 <= kp) + (b2 <= kp) + (b3 <= kp);
                if (kp > qp0 || sk != qsg0) s[nt][e]     = -INFINITY;
                if (kp > qp1 || sk != qsg1) s[nt][2 + e] = -INFINITY;
            }

        /* ---- online softmax (base-2 logits) ---- */
        float rm0 = -INFINITY, rm1 = -INFINITY;
#pragma unroll
        for (int nt = 0; nt < 4; nt++) {
            rm0 = fmaxf(rm0, fmaxf(s[nt][0], s[nt][1]));
            rm1 = fmaxf(rm1, fmaxf(s[nt][2], s[nt][3]));
        }
        rm0 = fmaxf(rm0, __shfl_xor_sync(0xffffffffu, rm0, 1));
        rm0 = fmaxf(rm0, __shfl_xor_sync(0xffffffffu, rm0, 2));
        rm1 = fmaxf(rm1, __shfl_xor_sync(0xffffffffu, rm1, 1));
        rm1 = fmaxf(rm1, __shfl_xor_sync(0xffffffffu, rm1, 2));
        float mn0 = fmaxf(m0, rm0), mn1 = fmaxf(m1, rm1);
        bool lv0 = mn0 > -INFINITY, lv1 = mn1 > -INFINITY;
        float sc0 = lv0 ? ((m0 > -INFINITY) ? ex2(m0 - mn0) : 0.f) : 1.f;
        float sc1 = lv1 ? ((m1 > -INFINITY) ? ex2(m1 - mn1) : 0.f) : 1.f;

        float p[4][4], pl[4][4];
        float rs0 = 0.f, rs1 = 0.f;
#pragma unroll
        for (int nt = 0; nt < 4; nt++) {
#pragma unroll
            for (int e = 0; e < 2; e++) {
                float v0 = lv0 ? ex2(s[nt][e]     - mn0) : 0.f;
                float v1 = lv1 ? ex2(s[nt][2 + e] - mn1) : 0.f;
                p[nt][e] = v0;     rs0 += v0;
                p[nt][2+e] = v1;   rs1 += v1;
            }
        }
        rs0 += __shfl_xor_sync(0xffffffffu, rs0, 1);
        rs0 += __shfl_xor_sync(0xffffffffu, rs0, 2);
        rs1 += __shfl_xor_sync(0xffffffffu, rs1, 1);
        rs1 += __shfl_xor_sync(0xffffffffu, rs1, 2);
        l0 = l0 * sc0 + rs0;  m0 = mn0;
        l1 = l1 * sc1 + rs1;  m1 = mn1;
#pragma unroll
        for (int nd = 0; nd < 8; nd++) {
            o[nd][0] *= sc0; o[nd][1] *= sc0;
            o[nd][2] *= sc1; o[nd][3] *= sc1;
        }

        /* P hi/lo */
#pragma unroll
        for (int nt = 0; nt < 4; nt++)
#pragma unroll
            for (int j = 0; j < 4; j++) {
                float hv = __bfloat162float(__float2bfloat16(p[nt][j]));
                pl[nt][j] = p[nt][j] - hv;
            }

        /* ---- O += P V (split 3-term) ---- */
#pragma unroll
        for (int kt2 = 0; kt2 < 2; kt2++) {
            uint32_t pah[4] = { pk(p[2*kt2][0],   p[2*kt2][1]),
                                pk(p[2*kt2][2],   p[2*kt2][3]),
                                pk(p[2*kt2+1][0], p[2*kt2+1][1]),
                                pk(p[2*kt2+1][2], p[2*kt2+1][3]) };
            uint32_t pal[4] = { pk(pl[2*kt2][0],   pl[2*kt2][1]),
                                pk(pl[2*kt2][2],   pl[2*kt2][3]),
                                pk(pl[2*kt2+1][0], pl[2*kt2+1][1]),
                                pk(pl[2*kt2+1][2], pl[2*kt2+1][3]) };
#pragma unroll
            for (int ndp = 0; ndp < 4; ndp++) {
                int mq = lane >> 3, r = lane & 7;
                uint32_t off = (uint32_t)(wk*32 + kt2*16 + ((mq & 1) ? 8 : 0) + r) * 144
                             + (ndp*16 + ((mq & 2) ? 8 : 0)) * 2;
                uint32_t vh4[4], vl4[4];
                ldmx4t(vh4, sb + AS_VH + off);
                ldmx4t(vl4, sb + AS_VL + off);
#pragma unroll
                for (int q2 = 0; q2 < 2; q2++) {
                    int nd = ndp*2 + q2;
                    mma16816(o[nd], pah, &vh4[q2*2]);
                    mma16816(o[nd], pah, &vl4[q2*2]);
                    mma16816(o[nd], pal, &vh4[q2*2]);
                }
            }
        }
    }

    /* ---- merge kv-halves (wk=1 -> smem -> wk=0), write output ---- */
    __syncthreads();
    float* Osm = (float*)smem;                   /* 64 x 68 */
    float* msm = (float*)(smem + 17408);         /* 64 */
    float* lsm = (float*)(smem + 17664);         /* 64 */
    int rl = wq*16 + (lane >> 2);
    int c2 = (lane & 3)*2;
    if (wk == 1) {
#pragma unroll
        for (int nd = 0; nd < 8; nd++) {
            *(float2*)&Osm[rl*68 + nd*8 + c2]     = make_float2(o[nd][0], o[nd][1]);
            *(float2*)&Osm[(rl+8)*68 + nd*8 + c2] = make_float2(o[nd][2], o[nd][3]);
        }
        if ((lane & 3) == 0) {
            msm[rl] = m0; msm[rl+8] = m1;
            lsm[rl] = l0; lsm[rl+8] = l1;
        }
    }
    __syncthreads();
    if (wk == 0) {
        float pm0 = msm[rl], pm1 = msm[rl+8];
        float pl0 = lsm[rl], pl1 = lsm[rl+8];
        float M0 = fmaxf(m0, pm0), M1 = fmaxf(m1, pm1);
        float sa0 = (m0  > -INFINITY) ? ex2(m0  - M0) : 0.f;
        float sb0 = (pm0 > -INFINITY) ? ex2(pm0 - M0) : 0.f;
        float sa1 = (m1  > -INFINITY) ? ex2(m1  - M1) : 0.f;
        float sb1 = (pm1 > -INFINITY) ? ex2(pm1 - M1) : 0.f;
        float inv0 = 1.f / (l0*sa0 + pl0*sb0);
        float inv1 = 1.f / (l1*sa1 + pl1*sb1);
        size_t r0g = (size_t)(b*SEQ + p0 + rl) * QDIM + h*HD;
        size_t r1g = (size_t)(b*SEQ + p0 + rl + 8) * QDIM + h*HD;
#pragma unroll
        for (int nd = 0; nd < 8; nd++) {
            float v0 = (o[nd][0]*sa0 + Osm[rl*68 + nd*8 + c2]*sb0) * inv0;
            float v1 = (o[nd][1]*sa0 + Osm[rl*68 + nd*8 + c2 + 1]*sb0) * inv0;
            float v2 = (o[nd][2]*sa1 + Osm[(rl+8)*68 + nd*8 + c2]*sb1) * inv1;
            float v3 = (o[nd][3]*sa1 + Osm[(rl+8)*68 + nd*8 + c2 + 1]*sb1) * inv1;
            float h0 = __bfloat162float(__float2bfloat16(v0));
            float h1 = __bfloat162float(__float2bfloat16(v1));
            float h2 = __bfloat162float(__float2bfloat16(v2));
            float h3 = __bfloat162float(__float2bfloat16(v3));
            *(uint32_t*)(g_aohi + r0g + nd*8 + c2) = pk(v0, v1);
            *(uint32_t*)(g_aolo + r0g + nd*8 + c2) = pk(v0 - h0, v1 - h1);
            *(uint32_t*)(g_aohi + r1g + nd*8 + c2) = pk(v2, v3);
            *(uint32_t*)(g_aolo + r1g + nd*8 + c2) = pk(v2 - h2, v3 - h3);
        }
    }
}

/* ------------------------------------------------------------------ */
extern "C" void kernel_launch(void* const* d_in, const int* in_sizes, int n_in,
                              void* d_out, int out_size) {
    const float* x  = (const float*)d_in[0];
    const int*   cu = (const int*)  d_in[1];
    const float* Wq = (const float*)d_in[2];
    const float* Wk = (const float*)d_in[3];
    const float* Wv = (const float*)d_in[4];
    const float* Wo = (const float*)d_in[5];
    float* out = (float*)d_out;

    float *q, *k, *v;
    __nv_bfloat16 *xhi, *xlo, *wqhi, *wqlo, *wkhi, *wklo, *wvhi, *wvlo, *wohi, *wolo;
    __nv_bfloat16 *aohi, *aolo, *vhi, *vlo;
    cudaGetSymbolAddress((void**)&q,  g_q);
    cudaGetSymbolAddress((void**)&k,  g_k);
    cudaGetSymbolAddress((void**)&v,  g_v);
    cudaGetSymbolAddress((void**)&xhi, g_xhi);   cudaGetSymbolAddress((void**)&xlo, g_xlo);
    cudaGetSymbolAddress((void**)&wqhi, g_wqhi); cudaGetSymbolAddress((void**)&wqlo, g_wqlo);
    cudaGetSymbolAddress((void**)&wkhi, g_wkhi); cudaGetSymbolAddress((void**)&wklo, g_wklo);
    cudaGetSymbolAddress((void**)&wvhi, g_wvhi); cudaGetSymbolAddress((void**)&wvlo, g_wvlo);
    cudaGetSymbolAddress((void**)&wohi, g_wohi); cudaGetSymbolAddress((void**)&wolo, g_wolo);
    cudaGetSymbolAddress((void**)&aohi, g_aohi); cudaGetSymbolAddress((void**)&aolo, g_aolo);
    cudaGetSymbolAddress((void**)&vhi, g_vhi);   cudaGetSymbolAddress((void**)&vlo, g_vlo);

    cudaFuncSetAttribute(attn_kernel,
                         cudaFuncAttributeMaxDynamicSharedMemorySize, ATTN_SMEM);
    cudaFuncSetAttribute(hmma_gemm,
                         cudaFuncAttributeMaxDynamicSharedMemorySize, GEMM_SMEM);

    /* 1-4: splits (launch #5 = big hmma_gemm, for ncu -s 5) */
    split_kernel<<<(NTOK*D_MODEL/4 + 255)/256, 256>>>(x, xhi, xlo, NTOK*D_MODEL/4);
    tsplit_kernel<<<dim3(QDIM /32, D_MODEL/32), dim3(32,8)>>>(Wq, wqhi, wqlo, D_MODEL, QDIM);
    tsplit_kernel<<<dim3(KVDIM/32, D_MODEL/32), dim3(32,8)>>>(Wk, wkhi, wklo, D_MODEL, KVDIM);
    tsplit_kernel<<<dim3(KVDIM/32, D_MODEL/32), dim3(32,8)>>>(Wv, wvhi, wvlo, D_MODEL, KVDIM);

    /* 5-7: QKV projections */
    hmma_gemm<<<dim3(QDIM /128, NTOK/128), 256, GEMM_SMEM>>>(xhi, xlo, wqhi, wqlo, q, NTOK, QDIM,  D_MODEL);
    hmma_gemm<<<dim3(KVDIM/128, NTOK/128), 256, GEMM_SMEM>>>(xhi, xlo, wkhi, wklo, k, NTOK, KVDIM, D_MODEL);
    hmma_gemm<<<dim3(KVDIM/128, NTOK/128), 256, GEMM_SMEM>>>(xhi, xlo, wvhi, wvlo, v, NTOK, KVDIM, D_MODEL);

    /* 8-11: Wo split, v split, rope */
    tsplit_kernel<<<dim3(D_MODEL/32, QDIM/32), dim3(32,8)>>>(Wo, wohi, wolo, QDIM, D_MODEL);
    split_kernel<<<(NTOK*KVDIM/4 + 255)/256, 256>>>(v, vhi, vlo, NTOK*KVDIM/4);
    rope_table_kernel<<<(SEQ*(HD/2) + 255)/256, 256>>>();
    rope_split_kernel<<<NTOK, 256>>>();

    /* 12: attention */
    attn_kernel<<<dim3(SEQ/64, N_HEADS, BATCH), 256, ATTN_SMEM>>>(cu);

    /* 13: output projection */
    hmma_gemm<<<dim3(D_MODEL/128, NTOK/128), 256, GEMM_SMEM>>>(aohi, aolo, wohi, wolo, out, NTOK, D_MODEL, QDIM);
}

// round 6
// speedup vs baseline: 4.2394x; 1.0580x over previous
#include <cuda_runtime.h>
#include <cuda_bf16.h>
#include <math.h>
#include <stdint.h>

#define D_MODEL 2048
#define N_HEADS 32
#define N_KV    8
#define HD      64
#define SEQ     2048
#define BATCH   2
#define NTOK    (BATCH*SEQ)      /* 4096 */
#define QDIM    (N_HEADS*HD)     /* 2048 */
#define KVDIM   (N_KV*HD)        /* 512  */
#define QKVDIM  (QDIM + 2*KVDIM) /* 3072 */
#define ROPE_BASE 500000.0
#define SCALE_L2E 0.1803368801111204f   /* 0.125 * log2(e) */

/* ---------------- static device scratch (no allocations) ---------------- */
__device__ float g_qkv[NTOK*QKVDIM];     /* merged q|k|v projection output */
__device__ float g_cos[SEQ*(HD/2)];
__device__ float g_sin[SEQ*(HD/2)];

__device__ __nv_bfloat16 g_xhi [NTOK*D_MODEL];
__device__ __nv_bfloat16 g_xlo [NTOK*D_MODEL];
__device__ __nv_bfloat16 g_wbhi[QKVDIM*D_MODEL];   /* packed Wq|Wk|Wv, [N,K] */
__device__ __nv_bfloat16 g_wblo[QKVDIM*D_MODEL];
__device__ __nv_bfloat16 g_wohi[D_MODEL*QDIM];
__device__ __nv_bfloat16 g_wolo[D_MODEL*QDIM];
__device__ __nv_bfloat16 g_aohi[NTOK*QDIM];
__device__ __nv_bfloat16 g_aolo[NTOK*QDIM];

/* attention operands, pre-split (rope-rotated; q pre-scaled) */
__device__ __nv_bfloat16 g_qhi[NTOK*QDIM];
__device__ __nv_bfloat16 g_qlo[NTOK*QDIM];
__device__ __nv_bfloat16 g_khi[NTOK*KVDIM];
__device__ __nv_bfloat16 g_klo[NTOK*KVDIM];
__device__ __nv_bfloat16 g_vhi[NTOK*KVDIM];
__device__ __nv_bfloat16 g_vlo[NTOK*KVDIM];

/* ---------------- PTX helpers ---------------- */
__device__ __forceinline__ uint32_t smem_u32(const void* p) {
    uint32_t a;
    asm("{ .reg .u64 t; cvta.to.shared.u64 t, %1; cvt.u32.u64 %0, t; }" : "=r"(a) : "l"(p));
    return a;
}
__device__ __forceinline__ void cp16(uint32_t saddr, const void* g) {
    asm volatile("cp.async.cg.shared.global [%0], [%1], 16;" :: "r"(saddr), "l"(g));
}
__device__ __forceinline__ void cp_commit() { asm volatile("cp.async.commit_group;" ::: "memory"); }
__device__ __forceinline__ void cp_wait0()  { asm volatile("cp.async.wait_group 0;"  ::: "memory"); }

__device__ __forceinline__ void ldmx4(uint32_t* r, uint32_t addr) {
    asm volatile("ldmatrix.sync.aligned.m8n8.x4.shared.b16 {%0,%1,%2,%3}, [%4];"
                 : "=r"(r[0]), "=r"(r[1]), "=r"(r[2]), "=r"(r[3]) : "r"(addr));
}
__device__ __forceinline__ void ldmx4t(uint32_t* r, uint32_t addr) {
    asm volatile("ldmatrix.sync.aligned.m8n8.x4.trans.shared.b16 {%0,%1,%2,%3}, [%4];"
                 : "=r"(r[0]), "=r"(r[1]), "=r"(r[2]), "=r"(r[3]) : "r"(addr));
}
__device__ __forceinline__ void mma16816(float* d, const uint32_t* a, const uint32_t* b) {
    asm volatile(
        "mma.sync.aligned.m16n8k16.row.col.f32.bf16.bf16.f32 "
        "{%0,%1,%2,%3}, {%4,%5,%6,%7}, {%8,%9}, {%0,%1,%2,%3};"
        : "+f"(d[0]), "+f"(d[1]), "+f"(d[2]), "+f"(d[3])
        : "r"(a[0]), "r"(a[1]), "r"(a[2]), "r"(a[3]), "r"(b[0]), "r"(b[1]));
}
__device__ __forceinline__ float ex2(float x) {
    float y; asm("ex2.approx.f32 %0, %1;" : "=f"(y) : "f"(x)); return y;
}
__device__ __forceinline__ uint32_t pk(float a, float b) {
    __nv_bfloat162 t = __float22bfloat162_rn(make_float2(a, b));
    return *(uint32_t*)&t;
}

/* ---------------- split kernels ---------------- */
__global__ __launch_bounds__(256) void split_kernel(const float* __restrict__ src,
                                                    __nv_bfloat16* __restrict__ hi,
                                                    __nv_bfloat16* __restrict__ lo,
                                                    int n4) {
    int i = blockIdx.x * blockDim.x + threadIdx.x;
    if (i >= n4) return;
    float4 v = ((const float4*)src)[i];
    __nv_bfloat16 h[4], l[4];
    float vv[4] = {v.x, v.y, v.z, v.w};
#pragma unroll
    for (int j = 0; j < 4; j++) {
        h[j] = __float2bfloat16(vv[j]);
        l[j] = __float2bfloat16(vv[j] - __bfloat162float(h[j]));
    }
    ((uint2*)hi)[i] = *(uint2*)h;
    ((uint2*)lo)[i] = *(uint2*)l;
}

/* transpose + split: W[K,N] fp32 -> hi/lo [nOff+N rows, K] bf16 */
__global__ __launch_bounds__(256) void tsplit_kernel(const float* __restrict__ W,
                                                     __nv_bfloat16* __restrict__ hi,
                                                     __nv_bfloat16* __restrict__ lo,
                                                     int K, int N, int nOff) {
    __shared__ float t[32][33];
    int n0 = blockIdx.x * 32, k0 = blockIdx.y * 32;
    int tx = threadIdx.x, ty = threadIdx.y;
#pragma unroll
    for (int i = 0; i < 32; i += 8)
        t[ty + i][tx] = W[(size_t)(k0 + ty + i) * N + n0 + tx];
    __syncthreads();
#pragma unroll
    for (int i = 0; i < 32; i += 8) {
        float v = t[tx][ty + i];
        __nv_bfloat16 h = __float2bfloat16(v);
        float r = v - __bfloat162float(h);
        size_t o = (size_t)(nOff + n0 + ty + i) * K + k0 + tx;
        hi[o] = h;
        lo[o] = __float2bfloat16(r);
    }
}

/* ---------------- bf16x3 HMMA GEMM, 64x64 warp tiles ----------------
 * CTA 128x128, BK=32, 128 threads (4 warps in 2x2), 2 CTAs/SM.
 */
#define TILE_B   10240            /* 128 rows * 80 B */
#define STAGE_B  (4*TILE_B)       /* AH AL BH BL = 40960 */
#define GEMM_SMEM (2*STAGE_B)     /* 81920 */

__global__ __launch_bounds__(128, 2)
void hmma_gemm(const __nv_bfloat16* __restrict__ Ahi, const __nv_bfloat16* __restrict__ Alo,
               const __nv_bfloat16* __restrict__ Bhi, const __nv_bfloat16* __restrict__ Blo,
               float* __restrict__ C, int M, int N, int K) {
    extern __shared__ char smem[];
    uint32_t sb = smem_u32(smem);
    int tid = threadIdx.x, lane = tid & 31, wid = tid >> 5;
    int wm = wid & 1, wn = wid >> 1;               /* 2 x 2 warp grid */
    int bm = blockIdx.y * 128, bn = blockIdx.x * 128;

    /* cp.async: per tile 128 rows x 64B; thread handles rows lr+{0,32,64,96} */
    int lr = tid >> 2;            /* 0..31 */
    int lc = tid & 3;             /* uint4 within 64B row */
    const __nv_bfloat16* gA1 = Ahi + (size_t)(bm + lr) * K + lc * 8;
    const __nv_bfloat16* gA2 = Alo + (size_t)(bm + lr) * K + lc * 8;
    const __nv_bfloat16* gB1 = Bhi + (size_t)(bn + lr) * K + lc * 8;
    const __nv_bfloat16* gB2 = Blo + (size_t)(bn + lr) * K + lc * 8;
    size_t rstep = (size_t)32 * K;
    uint32_t soff = lr * 80 + lc * 16;

#define LOAD_STAGE(st, koff)                                                      \
    do {                                                                          \
        _Pragma("unroll")                                                         \
        for (int r = 0; r < 4; r++) {                                             \
            uint32_t so = (st) + soff + r * 2560;                                 \
            cp16(so,              gA1 + r * rstep + (koff));                      \
            cp16(so + TILE_B,     gA2 + r * rstep + (koff));                      \
            cp16(so + 2*TILE_B,   gB1 + r * rstep + (koff));                      \
            cp16(so + 3*TILE_B,   gB2 + r * rstep + (koff));                      \
        }                                                                         \
    } while (0)

    float acc[4][8][4];
#pragma unroll
    for (int i = 0; i < 4; i++)
#pragma unroll
        for (int j = 0; j < 8; j++)
#pragma unroll
            for (int t = 0; t < 4; t++) acc[i][j][t] = 0.f;

    int nkt = K >> 5;

    LOAD_STAGE(sb, 0);
    cp_commit(); cp_wait0(); __syncthreads();

    uint32_t aBase = 2 * ((uint32_t)(wm * 64 + (lane & 15)) * 40 + ((lane >> 4) << 3));
    uint32_t bBase = 2 * ((uint32_t)(wn * 64 + (lane & 7) + ((lane >> 4) << 3)) * 40 + (lane & 8));

    for (int kt = 0; kt < nkt; kt++) {
        if (kt + 1 < nkt)
            LOAD_STAGE(sb + ((kt + 1) & 1) * STAGE_B, (kt + 1) << 5);
        cp_commit();

        uint32_t base = sb + (kt & 1) * STAGE_B;
#pragma unroll
        for (int kb = 0; kb < 32; kb += 16) {
            uint32_t ah[4][4], al[4][4], bh[4][4], bl[4][4];
#pragma unroll
            for (int mt = 0; mt < 4; mt++) {
                uint32_t o = aBase + 2 * (mt * 16 * 40 + kb);
                ldmx4(ah[mt], base + o);
                ldmx4(al[mt], base + TILE_B + o);
            }
#pragma unroll
            for (int g = 0; g < 4; g++) {
                uint32_t o = bBase + 2 * (g * 16 * 40 + kb);
                ldmx4(bh[g], base + 2*TILE_B + o);
                ldmx4(bl[g], base + 3*TILE_B + o);
            }
#pragma unroll
            for (int mt = 0; mt < 4; mt++)
#pragma unroll
                for (int nt = 0; nt < 8; nt++) {
                    const uint32_t* fh = &bh[nt >> 1][(nt & 1) * 2];
                    const uint32_t* fl = &bl[nt >> 1][(nt & 1) * 2];
                    mma16816(acc[mt][nt], ah[mt], fh);
                    mma16816(acc[mt][nt], ah[mt], fl);
                    mma16816(acc[mt][nt], al[mt], fh);
                }
        }
        cp_wait0();
        __syncthreads();
    }

    int er = lane >> 2, ec = (lane & 3) * 2;
#pragma unroll
    for (int mt = 0; mt < 4; mt++)
#pragma unroll
        for (int nt = 0; nt < 8; nt++) {
            int row = bm + wm * 64 + mt * 16 + er;
            int col = bn + wn * 64 + nt * 8 + ec;
            *(float2*)(C + (size_t)row * N + col) =
                make_float2(acc[mt][nt][0], acc[mt][nt][1]);
            *(float2*)(C + (size_t)(row + 8) * N + col) =
                make_float2(acc[mt][nt][2], acc[mt][nt][3]);
        }
#undef LOAD_STAGE
}

/* ---------------- RoPE ---------------- */
__global__ void rope_table_kernel() {
    int i = blockIdx.x * blockDim.x + threadIdx.x;
    if (i >= SEQ * (HD/2)) return;
    int t = i / (HD/2);
    int j = i % (HD/2);
    double inv = pow((double)ROPE_BASE, -(double)(2*j) / (double)HD);
    double ang = (double)t * inv;
    g_cos[i] = (float)cos(ang);
    g_sin[i] = (float)sin(ang);
}

/* rotate + (scale for q) + bf16 hi/lo split; reads merged g_qkv */
__global__ __launch_bounds__(256) void rope_split_kernel() {
    int tok = blockIdx.x;
    int s   = tok & (SEQ - 1);
    const float* src = g_qkv + (size_t)tok * QKVDIM;
    for (int pi = threadIdx.x; pi < (N_HEADS + N_KV) * (HD/2); pi += 256) {
        int head = pi >> 5;
        int j    = pi & 31;
        float c  = g_cos[s*32 + j];
        float sn = g_sin[s*32 + j];
        int scol;
        __nv_bfloat16 *hi, *lo;
        long dbase;
        float sc;
        if (head < N_HEADS) {
            scol = head*HD;
            hi = g_qhi; lo = g_qlo;
            dbase = (long)tok*QDIM + head*HD;
            sc = SCALE_L2E;
        } else {
            scol = QDIM + (head-N_HEADS)*HD;
            hi = g_khi; lo = g_klo;
            dbase = (long)tok*KVDIM + (head-N_HEADS)*HD;
            sc = 1.f;
        }
        float x1 = src[scol + j];
        float x2 = src[scol + j + 32];
        float r1 = (x1*c - x2*sn) * sc;
        float r2 = (x2*c + x1*sn) * sc;
        __nv_bfloat16 h1 = __float2bfloat16(r1);
        __nv_bfloat16 h2 = __float2bfloat16(r2);
        hi[dbase + j]      = h1;
        hi[dbase + j + 32] = h2;
        lo[dbase + j]      = __float2bfloat16(r1 - __bfloat162float(h1));
        lo[dbase + j + 32] = __float2bfloat16(r2 - __bfloat162float(h2));
    }
}

/* split v (strided out of merged qkv) */
__global__ __launch_bounds__(128) void vsplit_kernel() {
    int tok = blockIdx.x;
    int c4 = threadIdx.x;                /* 128 threads x 4 floats = 512 */
    float4 v = *(const float4*)(g_qkv + (size_t)tok*QKVDIM + QDIM + KVDIM + c4*4);
    float vv[4] = {v.x, v.y, v.z, v.w};
    __nv_bfloat16 h[4], l[4];
#pragma unroll
    for (int j = 0; j < 4; j++) {
        h[j] = __float2bfloat16(vv[j]);
        l[j] = __float2bfloat16(vv[j] - __bfloat162float(h[j]));
    }
    size_t o = (size_t)tok*KVDIM + c4*4;
    *(uint2*)(g_vhi + o) = *(uint2*)h;
    *(uint2*)(g_vlo + o) = *(uint2*)l;
}

/* ---------------- HMMA flash attention (unchanged from R5) ------------- */
#define AS_KH 0
#define AS_KL 9216
#define AS_VH 18432
#define AS_VL 27648
#define ATTN_SMEM 36864

__global__ __launch_bounds__(256)
void attn_kernel(const int* __restrict__ cu) {
    extern __shared__ char smem[];
    uint32_t sb = smem_u32(smem);
    int qb = blockIdx.x, h = blockIdx.y, b = blockIdx.z;
    int kvh = h >> 2;
    int tid = threadIdx.x, lane = tid & 31, wid = tid >> 5;
    int wq = wid & 3, wk = wid >> 2;

    int b0 = min(max(cu[b*4+0], 0), SEQ);
    int b1 = min(max(cu[b*4+1], 0), SEQ);
    int b2 = min(max(cu[b*4+2], 0), SEQ);
    int b3 = min(max(cu[b*4+3], 0), SEQ);

    int p0 = qb * 64;
    int s_start = 0;
    if (b0 <= p0) s_start = b0;
    if (b1 <= p0) s_start = max(s_start, b1);
    if (b2 <= p0) s_start = max(s_start, b2);
    if (b3 <= p0) s_start = max(s_start, b3);
    int kb0 = s_start >> 6;

#pragma unroll
    for (int i = 0; i < 4; i++) {
        int arr = i >> 1;
        int rem = tid + (i & 1) * 256;
        int row = rem >> 3, c = rem & 7;
        const __nv_bfloat16* src = arr ? g_qlo : g_qhi;
        cp16(sb + arr*9216 + row*144 + c*16,
             src + (size_t)(b*SEQ + p0 + row) * QDIM + h*HD + c*8);
    }
    cp_commit(); cp_wait0(); __syncthreads();

    uint32_t qh[4][4], ql[4][4];
#pragma unroll
    for (int kt = 0; kt < 4; kt++) {
        uint32_t off = (uint32_t)(wq*16 + (lane & 15)) * 144 + (kt*16 + ((lane >> 4) << 3)) * 2;
        ldmx4(qh[kt], sb + off);
        ldmx4(ql[kt], sb + 9216 + off);
    }

    int qp0 = p0 + wq*16 + (lane >> 2);
    int qp1 = qp0 + 8;
    int qsg0 = (b0 <= qp0) + (b1 <= qp0) + (b2 <= qp0) + (b3 <= qp0);
    int qsg1 = (b0 <= qp1) + (b1 <= qp1) + (b2 <= qp1) + (b3 <= qp1);

    float m0 = -INFINITY, m1 = -INFINITY, l0 = 0.f, l1 = 0.f;
    float o[8][4];
#pragma unroll
    for (int nd = 0; nd < 8; nd++)
#pragma unroll
        for (int j = 0; j < 4; j++) o[nd][j] = 0.f;

    int colb = wk*32 + (lane & 3)*2;

    for (int kb = kb0; kb <= qb; kb++) {
        __syncthreads();
#pragma unroll
        for (int i = 0; i < 8; i++) {
            int arr = i >> 1;
            int rem = tid + (i & 1) * 256;
            int row = rem >> 3, c = rem & 7;
            const __nv_bfloat16* src = (arr == 0) ? g_khi : (arr == 1) ? g_klo
                                     : (arr == 2) ? g_vhi : g_vlo;
            cp16(sb + arr*9216 + row*144 + c*16,
                 src + (size_t)(b*SEQ + kb*64 + row) * KVDIM + kvh*HD + c*8);
        }
        cp_commit(); cp_wait0(); __syncthreads();

        float s[4][4];
#pragma unroll
        for (int nt = 0; nt < 4; nt++)
#pragma unroll
            for (int j = 0; j < 4; j++) s[nt][j] = 0.f;

#pragma unroll
        for (int kt = 0; kt < 4; kt++) {
            uint32_t khf[2][4], klf[2][4];
#pragma unroll
            for (int np = 0; np < 2; np++) {
                int mq = lane >> 3, r = lane & 7;
                uint32_t off = (uint32_t)(wk*32 + np*16 + ((mq & 2) ? 8 : 0) + r) * 144
                             + (kt*16 + ((mq & 1) ? 8 : 0)) * 2;
                ldmx4(khf[np], sb + AS_KH + off);
                ldmx4(klf[np], sb + AS_KL + off);
            }
#pragma unroll
            for (int nt = 0; nt < 4; nt++) {
                const uint32_t* fh = &khf[nt >> 1][(nt & 1) * 2];
                const uint32_t* fl = &klf[nt >> 1][(nt & 1) * 2];
                mma16816(s[nt], qh[kt], fh);
                mma16816(s[nt], qh[kt], fl);
                mma16816(s[nt], ql[kt], fh);
            }
        }

#pragma unroll
        for (int nt = 0; nt < 4; nt++)
#pragma unroll
            for (int e = 0; e < 2; e++) {
                int kp = kb*64 + colb + nt*8 + e;
                int sk = (b0 <= kp) + (b1 <= kp) + (b2 <= kp) + (b3 <= kp);
                if (kp > qp0 || sk != qsg0) s[nt][e]     = -INFINITY;
                if (kp > qp1 || sk != qsg1) s[nt][2 + e] = -INFINITY;
            }

        float rm0 = -INFINITY, rm1 = -INFINITY;
#pragma unroll
        for (int nt = 0; nt < 4; nt++) {
            rm0 = fmaxf(rm0, fmaxf(s[nt][0], s[nt][1]));
            rm1 = fmaxf(rm1, fmaxf(s[nt][2], s[nt][3]));
        }
        rm0 = fmaxf(rm0, __shfl_xor_sync(0xffffffffu, rm0, 1));
        rm0 = fmaxf(rm0, __shfl_xor_sync(0xffffffffu, rm0, 2));
        rm1 = fmaxf(rm1, __shfl_xor_sync(0xffffffffu, rm1, 1));
        rm1 = fmaxf(rm1, __shfl_xor_sync(0xffffffffu, rm1, 2));
        float mn0 = fmaxf(m0, rm0), mn1 = fmaxf(m1, rm1);
        bool lv0 = mn0 > -INFINITY, lv1 = mn1 > -INFINITY;
        float sc0 = lv0 ? ((m0 > -INFINITY) ? ex2(m0 - mn0) : 0.f) : 1.f;
        float sc1 = lv1 ? ((m1 > -INFINITY) ? ex2(m1 - mn1) : 0.f) : 1.f;

        float p[4][4], pl[4][4];
        float rs0 = 0.f, rs1 = 0.f;
#pragma unroll
        for (int nt = 0; nt < 4; nt++) {
#pragma unroll
            for (int e = 0; e < 2; e++) {
                float v0 = lv0 ? ex2(s[nt][e]     - mn0) : 0.f;
                float v1 = lv1 ? ex2(s[nt][2 + e] - mn1) : 0.f;
                p[nt][e] = v0;     rs0 += v0;
                p[nt][2+e] = v1;   rs1 += v1;
            }
        }
        rs0 += __shfl_xor_sync(0xffffffffu, rs0, 1);
        rs0 += __shfl_xor_sync(0xffffffffu, rs0, 2);
        rs1 += __shfl_xor_sync(0xffffffffu, rs1, 1);
        rs1 += __shfl_xor_sync(0xffffffffu, rs1, 2);
        l0 = l0 * sc0 + rs0;  m0 = mn0;
        l1 = l1 * sc1 + rs1;  m1 = mn1;
#pragma unroll
        for (int nd = 0; nd < 8; nd++) {
            o[nd][0] *= sc0; o[nd][1] *= sc0;
            o[nd][2] *= sc1; o[nd][3] *= sc1;
        }

#pragma unroll
        for (int nt = 0; nt < 4; nt++)
#pragma unroll
            for (int j = 0; j < 4; j++) {
                float hv = __bfloat162float(__float2bfloat16(p[nt][j]));
                pl[nt][j] = p[nt][j] - hv;
            }

#pragma unroll
        for (int kt2 = 0; kt2 < 2; kt2++) {
            uint32_t pah[4] = { pk(p[2*kt2][0],   p[2*kt2][1]),
                                pk(p[2*kt2][2],   p[2*kt2][3]),
                                pk(p[2*kt2+1][0], p[2*kt2+1][1]),
                                pk(p[2*kt2+1][2], p[2*kt2+1][3]) };
            uint32_t pal[4] = { pk(pl[2*kt2][0],   pl[2*kt2][1]),
                                pk(pl[2*kt2][2],   pl[2*kt2][3]),
                                pk(pl[2*kt2+1][0], pl[2*kt2+1][1]),
                                pk(pl[2*kt2+1][2], pl[2*kt2+1][3]) };
#pragma unroll
            for (int ndp = 0; ndp < 4; ndp++) {
                int mq = lane >> 3, r = lane & 7;
                uint32_t off = (uint32_t)(wk*32 + kt2*16 + ((mq & 1) ? 8 : 0) + r) * 144
                             + (ndp*16 + ((mq & 2) ? 8 : 0)) * 2;
                uint32_t vh4[4], vl4[4];
                ldmx4t(vh4, sb + AS_VH + off);
                ldmx4t(vl4, sb + AS_VL + off);
#pragma unroll
                for (int q2 = 0; q2 < 2; q2++) {
                    int nd = ndp*2 + q2;
                    mma16816(o[nd], pah, &vh4[q2*2]);
                    mma16816(o[nd], pah, &vl4[q2*2]);
                    mma16816(o[nd], pal, &vh4[q2*2]);
                }
            }
        }
    }

    __syncthreads();
    float* Osm = (float*)smem;
    float* msm = (float*)(smem + 17408);
    float* lsm = (float*)(smem + 17664);
    int rl = wq*16 + (lane >> 2);
    int c2 = (lane & 3)*2;
    if (wk == 1) {
#pragma unroll
        for (int nd = 0; nd < 8; nd++) {
            *(float2*)&Osm[rl*68 + nd*8 + c2]     = make_float2(o[nd][0], o[nd][1]);
            *(float2*)&Osm[(rl+8)*68 + nd*8 + c2] = make_float2(o[nd][2], o[nd][3]);
        }
        if ((lane & 3) == 0) {
            msm[rl] = m0; msm[rl+8] = m1;
            lsm[rl] = l0; lsm[rl+8] = l1;
        }
    }
    __syncthreads();
    if (wk == 0) {
        float pm0 = msm[rl], pm1 = msm[rl+8];
        float pl0 = lsm[rl], pl1 = lsm[rl+8];
        float M0 = fmaxf(m0, pm0), M1 = fmaxf(m1, pm1);
        float sa0 = (m0  > -INFINITY) ? ex2(m0  - M0) : 0.f;
        float sb0 = (pm0 > -INFINITY) ? ex2(pm0 - M0) : 0.f;
        float sa1 = (m1  > -INFINITY) ? ex2(m1  - M1) : 0.f;
        float sb1 = (pm1 > -INFINITY) ? ex2(pm1 - M1) : 0.f;
        float inv0 = 1.f / (l0*sa0 + pl0*sb0);
        float inv1 = 1.f / (l1*sa1 + pl1*sb1);
        size_t r0g = (size_t)(b*SEQ + p0 + rl) * QDIM + h*HD;
        size_t r1g = (size_t)(b*SEQ + p0 + rl + 8) * QDIM + h*HD;
#pragma unroll
        for (int nd = 0; nd < 8; nd++) {
            float v0 = (o[nd][0]*sa0 + Osm[rl*68 + nd*8 + c2]*sb0) * inv0;
            float v1 = (o[nd][1]*sa0 + Osm[rl*68 + nd*8 + c2 + 1]*sb0) * inv0;
            float v2 = (o[nd][2]*sa1 + Osm[(rl+8)*68 + nd*8 + c2]*sb1) * inv1;
            float v3 = (o[nd][3]*sa1 + Osm[(rl+8)*68 + nd*8 + c2 + 1]*sb1) * inv1;
            float h0 = __bfloat162float(__float2bfloat16(v0));
            float h1 = __bfloat162float(__float2bfloat16(v1));
            float h2 = __bfloat162float(__float2bfloat16(v2));
            float h3 = __bfloat162float(__float2bfloat16(v3));
            *(uint32_t*)(g_aohi + r0g + nd*8 + c2) = pk(v0, v1);
            *(uint32_t*)(g_aolo + r0g + nd*8 + c2) = pk(v0 - h0, v1 - h1);
            *(uint32_t*)(g_aohi + r1g + nd*8 + c2) = pk(v2, v3);
            *(uint32_t*)(g_aolo + r1g + nd*8 + c2) = pk(v2 - h2, v3 - h3);
        }
    }
}

/* ------------------------------------------------------------------ */
extern "C" void kernel_launch(void* const* d_in, const int* in_sizes, int n_in,
                              void* d_out, int out_size) {
    const float* x  = (const float*)d_in[0];
    const int*   cu = (const int*)  d_in[1];
    const float* Wq = (const float*)d_in[2];
    const float* Wk = (const float*)d_in[3];
    const float* Wv = (const float*)d_in[4];
    const float* Wo = (const float*)d_in[5];
    float* out = (float*)d_out;

    float *qkv;
    __nv_bfloat16 *xhi, *xlo, *wbhi, *wblo, *wohi, *wolo, *aohi, *aolo;
    cudaGetSymbolAddress((void**)&qkv, g_qkv);
    cudaGetSymbolAddress((void**)&xhi, g_xhi);   cudaGetSymbolAddress((void**)&xlo, g_xlo);
    cudaGetSymbolAddress((void**)&wbhi, g_wbhi); cudaGetSymbolAddress((void**)&wblo, g_wblo);
    cudaGetSymbolAddress((void**)&wohi, g_wohi); cudaGetSymbolAddress((void**)&wolo, g_wolo);
    cudaGetSymbolAddress((void**)&aohi, g_aohi); cudaGetSymbolAddress((void**)&aolo, g_aolo);

    cudaFuncSetAttribute(attn_kernel,
                         cudaFuncAttributeMaxDynamicSharedMemorySize, ATTN_SMEM);
    cudaFuncSetAttribute(hmma_gemm,
                         cudaFuncAttributeMaxDynamicSharedMemorySize, GEMM_SMEM);

    /* splits: x; packed Wq|Wk|Wv; Wo */
    split_kernel<<<(NTOK*D_MODEL/4 + 255)/256, 256>>>(x, xhi, xlo, NTOK*D_MODEL/4);
    tsplit_kernel<<<dim3(QDIM /32, D_MODEL/32), dim3(32,8)>>>(Wq, wbhi, wblo, D_MODEL, QDIM,  0);
    tsplit_kernel<<<dim3(KVDIM/32, D_MODEL/32), dim3(32,8)>>>(Wk, wbhi, wblo, D_MODEL, KVDIM, QDIM);
    tsplit_kernel<<<dim3(KVDIM/32, D_MODEL/32), dim3(32,8)>>>(Wv, wbhi, wblo, D_MODEL, KVDIM, QDIM+KVDIM);
    tsplit_kernel<<<dim3(D_MODEL/32, QDIM/32), dim3(32,8)>>>(Wo, wohi, wolo, QDIM, D_MODEL, 0);

    /* merged QKV projection */
    hmma_gemm<<<dim3(QKVDIM/128, NTOK/128), 128, GEMM_SMEM>>>(xhi, xlo, wbhi, wblo, qkv,
                                                              NTOK, QKVDIM, D_MODEL);

    /* RoPE + operand splits */
    rope_table_kernel<<<(SEQ*(HD/2) + 255)/256, 256>>>();
    rope_split_kernel<<<NTOK, 256>>>();
    vsplit_kernel<<<NTOK, 128>>>();

    /* attention */
    attn_kernel<<<dim3(SEQ/64, N_HEADS, BATCH), 256, ATTN_SMEM>>>(cu);

    /* output projection */
    hmma_gemm<<<dim3(D_MODEL/128, NTOK/128), 128, GEMM_SMEM>>>(aohi, aolo, wohi, wolo, out,
                                                               NTOK, D_MODEL, QDIM);
}